// round 3
// baseline (speedup 1.0000x reference)
#include <cuda_runtime.h>
#include <math.h>

#define BB 32
#define FF 128
#define HH 256
#define NPTS 2048
#define SD 3
#define LAYERS 2
#define NE 262144
#define NN (BB*NPTS)      // 65536
#define TE 16
#define FSTRIDE 516       // 513 padded to mult of 4 (16B-aligned float4 rows)
#define USTRIDE 512

typedef unsigned long long u64;

// packed f32x2 helpers (sm_100+ PTX; ptxas never auto-emits these)
__device__ __forceinline__ u64 pack2(float lo, float hi) {
    u64 r;
    asm("mov.b64 %0, {%1, %2};" : "=l"(r) : "f"(lo), "f"(hi));
    return r;
}
__device__ __forceinline__ void fma2(u64& acc, u64 a, u64 b) {
    asm("fma.rn.f32x2 %0, %1, %2, %0;" : "+l"(acc) : "l"(a), "l"(b));
}
__device__ __forceinline__ float hsum2(u64 v) {
    float lo, hi;
    asm("mov.b64 {%0, %1}, %2;" : "=f"(lo), "=f"(hi) : "l"(v));
    return lo + hi;
}

// ---------------- scratch (device globals; no allocation allowed) ----------
__device__ float g_h0[BB*HH];
__device__ float g_meand[NPTS];
__device__ float g_g[NPTS*HH];
__device__ float g_h[NN*HH];       // 64 MB
__device__ float g_pos[NN*SD];
__device__ float g_agg[NN*HH];     // 64 MB
__device__ float g_dpos[NN*SD];

// ---------------- zero agg + dpos -------------------------------------------
__global__ void k_zero()
{
    int i = blockIdx.x * blockDim.x + threadIdx.x;
    int stride = gridDim.x * blockDim.x;
    for (int k = i; k < NN*HH; k += stride) g_agg[k] = 0.f;
    for (int k = i; k < NN*SD; k += stride) g_dpos[k] = 0.f;
}

// ---------------- h0 = x @ W_in + b_in  [32,256] ---------------------------
__global__ void k_h0(const float* __restrict__ x, const float* __restrict__ W,
                     const float* __restrict__ b)
{
    int bi = blockIdx.x, j = threadIdx.x;
    __shared__ float xr[FF];
    if (j < FF) xr[j] = x[bi*FF + j];
    __syncthreads();
    float acc = b[j];
    #pragma unroll 4
    for (int k = 0; k < FF; k++) acc = fmaf(xr[k], W[k*HH + j], acc);
    g_h0[bi*HH + j] = acc;
}

// ---------------- mean pairwise distance per point --------------------------
__global__ void k_meand(const float* __restrict__ P)
{
    int i = blockIdx.x;
    float px = P[i*3+0], py = P[i*3+1], pz = P[i*3+2];
    float s = 0.f;
    for (int j = threadIdx.x; j < NPTS; j += 256) {
        if (j == i) continue;
        float dx = px - P[j*3+0], dy = py - P[j*3+1], dz = pz - P[j*3+2];
        s += sqrtf(dx*dx + dy*dy + dz*dz);
    }
    __shared__ float red[256];
    red[threadIdx.x] = s;
    __syncthreads();
    for (int st = 128; st > 0; st >>= 1) {
        if (threadIdx.x < st) red[threadIdx.x] += red[threadIdx.x + st];
        __syncthreads();
    }
    if (threadIdx.x == 0) g_meand[i] = red[0] / (float)(NPTS - 1);
}

// ------- g = relu(gf@Wg1+bg1)@Wg2+bg2, gf cols are all mean_d ---------------
__global__ void k_geo(const float* __restrict__ Wg1, const float* __restrict__ bg1,
                      const float* __restrict__ Wg2, const float* __restrict__ bg2)
{
    int i = blockIdx.x, j = threadIdx.x;
    __shared__ float t[FF];
    float m = g_meand[i];
    if (j < FF) {
        float ws = Wg1[j] + Wg1[FF + j] + Wg1[2*FF + j];
        t[j] = fmaxf(fmaf(m, ws, bg1[j]), 0.f);
    }
    __syncthreads();
    float acc = bg2[j];
    #pragma unroll 4
    for (int k = 0; k < FF; k++) acc = fmaf(t[k], Wg2[k*HH + j], acc);
    g_g[i*HH + j] = acc;
}

// ---------------- init node features & positions ----------------------------
__global__ void k_init(const float* __restrict__ P)
{
    int bn = blockIdx.x, j = threadIdx.x;
    int b = bn >> 11, n = bn & (NPTS - 1);
    g_h[bn*HH + j] = g_h0[b*HH + j] + g_g[n*HH + j];
    if (j < SD) g_pos[bn*SD + j] = P[n*SD + j];
}

// ---------------- message kernel: per 16-edge tile --------------------------
// m = relu([h_src; h_dst; d] @ Wm + bm); agg[dst] += m;
// coef = m @ Wp; dpos[dst] += (pos_dst - pos_src) * coef
__global__ void __launch_bounds__(256) msg_kernel(
    const int* __restrict__ src, const int* __restrict__ dst,
    const float* __restrict__ Wm, const float* __restrict__ bm,
    const float* __restrict__ Wp)
{
    __shared__ __align__(16) float sm[TE * FSTRIDE];   // 33024 B
    __shared__ int ssrc[TE], sdst[TE];
    __shared__ float spart[8][TE];
    int tid = threadIdx.x;
    int e0 = blockIdx.x * TE;

    if (tid < TE) { ssrc[tid] = src[e0 + tid]; sdst[tid] = dst[e0 + tid]; }
    __syncthreads();

    #pragma unroll 4
    for (int e = 0; e < TE; e++) {
        sm[e*FSTRIDE + tid]      = g_h[ssrc[e]*HH + tid];
        sm[e*FSTRIDE + HH + tid] = g_h[sdst[e]*HH + tid];
    }
    if (tid < TE) {
        int s = ssrc[tid], t = sdst[tid];
        float dx = g_pos[s*3+0] - g_pos[t*3+0];
        float dy = g_pos[s*3+1] - g_pos[t*3+1];
        float dz = g_pos[s*3+2] - g_pos[t*3+2];
        sm[tid*FSTRIDE + 512] = sqrtf(dx*dx + dy*dy + dz*dz + 1e-12f);
    }
    __syncthreads();

    // packed f32x2 accumulators: lo lane = even-k partial, hi lane = odd-k partial
    u64 acc[TE];
    #pragma unroll
    for (int e = 0; e < TE; e++) acc[e] = 0ull;

    const float* wc = Wm + tid;              // column tid, stride HH
    for (int k4 = 0; k4 < 128; k4++) {
        float w0 = wc[(4*k4 + 0)*HH];
        float w1 = wc[(4*k4 + 1)*HH];
        float w2 = wc[(4*k4 + 2)*HH];
        float w3 = wc[(4*k4 + 3)*HH];
        u64 w01 = pack2(w0, w1);
        u64 w23 = pack2(w2, w3);
        #pragma unroll
        for (int e = 0; e < TE; e++) {
            ulonglong2 f = *(const ulonglong2*)(sm + e*FSTRIDE + 4*k4);
            fma2(acc[e], f.x, w01);
            fma2(acc[e], f.y, w23);
        }
    }
    float wd = wc[512*HH];
    float bj = bm[tid];
    float m_[TE];
    #pragma unroll
    for (int e = 0; e < TE; e++) {
        float a = hsum2(acc[e]);
        a = fmaf(sm[e*FSTRIDE + 512], wd, a);
        m_[e] = fmaxf(a + bj, 0.f);
    }

    // segment-sum of messages into agg[dst]
    #pragma unroll 4
    for (int e = 0; e < TE; e++) atomicAdd(g_agg + sdst[e]*HH + tid, m_[e]);

    // coef[e] = sum_j m[e][j] * Wp[j]  (cross-thread reduce)
    float wp = Wp[tid];
    int lane = tid & 31, wrp = tid >> 5;
    #pragma unroll
    for (int e = 0; e < TE; e++) {
        float v = m_[e] * wp;
        v += __shfl_xor_sync(0xffffffffu, v, 16);
        v += __shfl_xor_sync(0xffffffffu, v, 8);
        v += __shfl_xor_sync(0xffffffffu, v, 4);
        v += __shfl_xor_sync(0xffffffffu, v, 2);
        v += __shfl_xor_sync(0xffffffffu, v, 1);
        if (lane == 0) spart[wrp][e] = v;
    }
    __syncthreads();
    if (tid < TE) {
        float c = spart[0][tid] + spart[1][tid] + spart[2][tid] + spart[3][tid]
                + spart[4][tid] + spart[5][tid] + spart[6][tid] + spart[7][tid];
        int s = ssrc[tid], t = sdst[tid];
        atomicAdd(g_dpos + t*3+0, (g_pos[t*3+0] - g_pos[s*3+0]) * c);
        atomicAdd(g_dpos + t*3+1, (g_pos[t*3+1] - g_pos[s*3+1]) * c);
        atomicAdd(g_dpos + t*3+2, (g_pos[t*3+2] - g_pos[s*3+2]) * c);
    }
}

// ---------------- update kernel: per 16-node tile ---------------------------
// h += relu([h; agg] @ Wu + bu); pos += dpos / DEG
__global__ void __launch_bounds__(256) upd_kernel(
    const float* __restrict__ Wu, const float* __restrict__ bu)
{
    __shared__ __align__(16) float sm[TE * USTRIDE];   // 32768 B
    int tid = threadIdx.x;
    int n0 = blockIdx.x * TE;

    #pragma unroll 4
    for (int e = 0; e < TE; e++) {
        sm[e*USTRIDE + tid]      = g_h[(n0 + e)*HH + tid];
        sm[e*USTRIDE + HH + tid] = g_agg[(n0 + e)*HH + tid];
    }
    __syncthreads();

    u64 acc[TE];
    #pragma unroll
    for (int e = 0; e < TE; e++) acc[e] = 0ull;

    const float* wc = Wu + tid;
    for (int k4 = 0; k4 < 128; k4++) {
        float w0 = wc[(4*k4 + 0)*HH];
        float w1 = wc[(4*k4 + 1)*HH];
        float w2 = wc[(4*k4 + 2)*HH];
        float w3 = wc[(4*k4 + 3)*HH];
        u64 w01 = pack2(w0, w1);
        u64 w23 = pack2(w2, w3);
        #pragma unroll
        for (int e = 0; e < TE; e++) {
            ulonglong2 f = *(const ulonglong2*)(sm + e*USTRIDE + 4*k4);
            fma2(acc[e], f.x, w01);
            fma2(acc[e], f.y, w23);
        }
    }
    float bj = bu[tid];
    #pragma unroll
    for (int e = 0; e < TE; e++) {
        float a = hsum2(acc[e]);
        g_h[(n0 + e)*HH + tid] = sm[e*USTRIDE + tid] + fmaxf(a + bj, 0.f);
    }

    if (tid < TE*SD) {
        int n = n0 + tid / 3, c = tid % 3;
        g_pos[n*3 + c] += g_dpos[n*3 + c] * 0.25f;   // 1/DEG, DEG = E/(B*N) = 4
    }
}

// ---------------- output: out[bn] = h[bn] . W_out + b_out -------------------
__global__ void k_out(const float* __restrict__ Wo, const float* __restrict__ bo,
                      float* __restrict__ out)
{
    int lane = threadIdx.x & 31;
    int node = blockIdx.x * 8 + (threadIdx.x >> 5);
    float v = 0.f;
    #pragma unroll
    for (int r = 0; r < 8; r++) {
        int j = lane + r*32;
        v = fmaf(g_h[node*HH + j], Wo[j], v);
    }
    v += __shfl_xor_sync(0xffffffffu, v, 16);
    v += __shfl_xor_sync(0xffffffffu, v, 8);
    v += __shfl_xor_sync(0xffffffffu, v, 4);
    v += __shfl_xor_sync(0xffffffffu, v, 2);
    v += __shfl_xor_sync(0xffffffffu, v, 1);
    if (lane == 0) out[node] = v + bo[0];
}

// ---------------------------------------------------------------------------
extern "C" void kernel_launch(void* const* d_in, const int* in_sizes, int n_in,
                              void* d_out, int out_size)
{
    const float* x         = (const float*)d_in[0];
    const float* positions = (const float*)d_in[1];
    const float* W_in      = (const float*)d_in[2];
    const float* b_in      = (const float*)d_in[3];
    const float* Wg1       = (const float*)d_in[4];
    const float* bg1       = (const float*)d_in[5];
    const float* Wg2       = (const float*)d_in[6];
    const float* bg2       = (const float*)d_in[7];
    const float* Wm        = (const float*)d_in[8];
    const float* bm        = (const float*)d_in[9];
    const float* Wu        = (const float*)d_in[10];
    const float* bu        = (const float*)d_in[11];
    const float* Wp        = (const float*)d_in[12];
    const float* W_out     = (const float*)d_in[13];
    const float* b_out     = (const float*)d_in[14];
    const int*   edge      = (const int*)d_in[15];
    float* out = (float*)d_out;

    k_h0<<<BB, 256>>>(x, W_in, b_in);
    k_meand<<<NPTS, 256>>>(positions);
    k_geo<<<NPTS, 256>>>(Wg1, bg1, Wg2, bg2);
    k_init<<<NN, 256>>>(positions);

    const int* srcp = edge;
    const int* dstp = edge + NE;
    for (int l = 0; l < LAYERS; l++) {
        k_zero<<<592, 256>>>();
        msg_kernel<<<NE/TE, 256>>>(srcp, dstp,
                                   Wm + (size_t)l*513*HH, bm + l*HH, Wp + l*HH);
        upd_kernel<<<NN/TE, 256>>>(Wu + (size_t)l*512*HH, bu + l*HH);
    }
    k_out<<<NN/8, 256>>>(W_out, b_out, out);
}

// round 5
// speedup vs baseline: 2.5074x; 2.5074x over previous
#include <cuda_runtime.h>
#include <math.h>

#define BB 32
#define FF 128
#define HH 256
#define NPTS 2048
#define SD 3
#define LAYERS 2
#define NE 262144
#define NN (BB*NPTS)      // 65536
#define TE 16
#define USTRIDE 512

// ---------------- scratch (device globals; no allocation allowed) ----------
__device__ float g_h0[BB*HH];
__device__ float g_meand[NPTS];
__device__ float g_g[NPTS*HH];
__device__ float g_h[NN*HH];       // 64 MB
__device__ float g_P[NN*HH];       // 64 MB: H @ Wm_top
__device__ float g_Q[NN*HH];       // 64 MB: H @ Wm_mid
__device__ float g_pos[NN*SD];
__device__ float g_agg[NN*HH];     // 64 MB
__device__ float g_dpos[NN*SD];

// ---------------- zero agg + dpos -------------------------------------------
__global__ void k_zero()
{
    int i = blockIdx.x * blockDim.x + threadIdx.x;
    int stride = gridDim.x * blockDim.x;
    for (int k = i; k < NN*HH; k += stride) g_agg[k] = 0.f;
    for (int k = i; k < NN*SD; k += stride) g_dpos[k] = 0.f;
}

// ---------------- h0 = x @ W_in + b_in  [32,256] ---------------------------
__global__ void k_h0(const float* __restrict__ x, const float* __restrict__ W,
                     const float* __restrict__ b)
{
    int bi = blockIdx.x, j = threadIdx.x;
    __shared__ float xr[FF];
    if (j < FF) xr[j] = x[bi*FF + j];
    __syncthreads();
    float acc = b[j];
    #pragma unroll 4
    for (int k = 0; k < FF; k++) acc = fmaf(xr[k], W[k*HH + j], acc);
    g_h0[bi*HH + j] = acc;
}

// ---------------- mean pairwise distance per point --------------------------
__global__ void k_meand(const float* __restrict__ P)
{
    int i = blockIdx.x;
    float px = P[i*3+0], py = P[i*3+1], pz = P[i*3+2];
    float s = 0.f;
    for (int j = threadIdx.x; j < NPTS; j += 256) {
        if (j == i) continue;
        float dx = px - P[j*3+0], dy = py - P[j*3+1], dz = pz - P[j*3+2];
        s += sqrtf(dx*dx + dy*dy + dz*dz);
    }
    __shared__ float red[256];
    red[threadIdx.x] = s;
    __syncthreads();
    for (int st = 128; st > 0; st >>= 1) {
        if (threadIdx.x < st) red[threadIdx.x] += red[threadIdx.x + st];
        __syncthreads();
    }
    if (threadIdx.x == 0) g_meand[i] = red[0] / (float)(NPTS - 1);
}

// ------- g = relu(gf@Wg1+bg1)@Wg2+bg2, gf cols are all mean_d ---------------
__global__ void k_geo(const float* __restrict__ Wg1, const float* __restrict__ bg1,
                      const float* __restrict__ Wg2, const float* __restrict__ bg2)
{
    int i = blockIdx.x, j = threadIdx.x;
    __shared__ float t[FF];
    float m = g_meand[i];
    if (j < FF) {
        float ws = Wg1[j] + Wg1[FF + j] + Wg1[2*FF + j];
        t[j] = fmaxf(fmaf(m, ws, bg1[j]), 0.f);
    }
    __syncthreads();
    float acc = bg2[j];
    #pragma unroll 4
    for (int k = 0; k < FF; k++) acc = fmaf(t[k], Wg2[k*HH + j], acc);
    g_g[i*HH + j] = acc;
}

// ---------------- init node features & positions ----------------------------
__global__ void k_init(const float* __restrict__ P)
{
    int bn = blockIdx.x, j = threadIdx.x;
    int b = bn >> 11, n = bn & (NPTS - 1);
    g_h[bn*HH + j] = g_h0[b*HH + j] + g_g[n*HH + j];
    if (j < SD) g_pos[bn*SD + j] = P[n*SD + j];
}

// ---------------- PQ kernel: per 16-node tile -------------------------------
// P = H @ Wm[0:256], Q = H @ Wm[256:512]  (shared h-tile, dual accumulators)
__global__ void __launch_bounds__(256) pq_kernel(const float* __restrict__ Wm)
{
    __shared__ __align__(16) float sm[TE * HH];   // 16 KB
    int tid = threadIdx.x;
    int n0 = blockIdx.x * TE;

    #pragma unroll 4
    for (int e = 0; e < TE; e++)
        sm[e*HH + tid] = g_h[(n0 + e)*HH + tid];
    __syncthreads();

    float accP[TE], accQ[TE];
    #pragma unroll
    for (int e = 0; e < TE; e++) { accP[e] = 0.f; accQ[e] = 0.f; }

    const float* wt = Wm + tid;                 // top block, column tid
    const float* wq = Wm + (size_t)HH*HH + tid; // mid block, column tid
    for (int k4 = 0; k4 < HH/4; k4++) {
        float t0 = wt[(4*k4 + 0)*HH];
        float t1 = wt[(4*k4 + 1)*HH];
        float t2 = wt[(4*k4 + 2)*HH];
        float t3 = wt[(4*k4 + 3)*HH];
        float q0 = wq[(4*k4 + 0)*HH];
        float q1 = wq[(4*k4 + 1)*HH];
        float q2 = wq[(4*k4 + 2)*HH];
        float q3 = wq[(4*k4 + 3)*HH];
        #pragma unroll
        for (int e = 0; e < TE; e++) {
            float4 f = *(const float4*)(sm + e*HH + 4*k4);
            accP[e] = fmaf(f.w, t3, fmaf(f.z, t2, fmaf(f.y, t1, fmaf(f.x, t0, accP[e]))));
            accQ[e] = fmaf(f.w, q3, fmaf(f.z, q2, fmaf(f.y, q1, fmaf(f.x, q0, accQ[e]))));
        }
    }
    #pragma unroll
    for (int e = 0; e < TE; e++) {
        g_P[(n0 + e)*HH + tid] = accP[e];
        g_Q[(n0 + e)*HH + tid] = accQ[e];
    }
}

// ---------------- edgewise kernel: per 16-edge tile -------------------------
// m = relu(P[src] + Q[dst] + d*w_d + bm); agg[dst] += m;
// coef = m @ Wp; dpos[dst] += (pos_dst - pos_src) * coef
__global__ void __launch_bounds__(256) edge_kernel(
    const int* __restrict__ src, const int* __restrict__ dst,
    const float* __restrict__ Wm, const float* __restrict__ bm,
    const float* __restrict__ Wp)
{
    __shared__ int ssrc[TE], sdst[TE];
    __shared__ float sd[TE];
    __shared__ float spart[8][TE];
    int tid = threadIdx.x;
    int e0 = blockIdx.x * TE;

    if (tid < TE) {
        int s = src[e0 + tid], t = dst[e0 + tid];
        ssrc[tid] = s; sdst[tid] = t;
        float dx = g_pos[s*3+0] - g_pos[t*3+0];
        float dy = g_pos[s*3+1] - g_pos[t*3+1];
        float dz = g_pos[s*3+2] - g_pos[t*3+2];
        sd[tid] = sqrtf(dx*dx + dy*dy + dz*dz + 1e-12f);
    }
    __syncthreads();

    float wd = Wm[(size_t)512*HH + tid];
    float bj = bm[tid];
    float wp = Wp[tid];

    float m_[TE];
    #pragma unroll 4
    for (int e = 0; e < TE; e++) {
        float v = g_P[ssrc[e]*HH + tid] + g_Q[sdst[e]*HH + tid];
        v = fmaf(sd[e], wd, v) + bj;
        m_[e] = fmaxf(v, 0.f);
    }

    // segment-sum of messages into agg[dst]
    #pragma unroll 4
    for (int e = 0; e < TE; e++) atomicAdd(g_agg + sdst[e]*HH + tid, m_[e]);

    // coef[e] = sum_j m[e][j] * Wp[j]  (cross-thread reduce)
    int lane = tid & 31, wrp = tid >> 5;
    #pragma unroll
    for (int e = 0; e < TE; e++) {
        float v = m_[e] * wp;
        v += __shfl_xor_sync(0xffffffffu, v, 16);
        v += __shfl_xor_sync(0xffffffffu, v, 8);
        v += __shfl_xor_sync(0xffffffffu, v, 4);
        v += __shfl_xor_sync(0xffffffffu, v, 2);
        v += __shfl_xor_sync(0xffffffffu, v, 1);
        if (lane == 0) spart[wrp][e] = v;
    }
    __syncthreads();
    if (tid < TE) {
        float c = spart[0][tid] + spart[1][tid] + spart[2][tid] + spart[3][tid]
                + spart[4][tid] + spart[5][tid] + spart[6][tid] + spart[7][tid];
        int s = ssrc[tid], t = sdst[tid];
        atomicAdd(g_dpos + t*3+0, (g_pos[t*3+0] - g_pos[s*3+0]) * c);
        atomicAdd(g_dpos + t*3+1, (g_pos[t*3+1] - g_pos[s*3+1]) * c);
        atomicAdd(g_dpos + t*3+2, (g_pos[t*3+2] - g_pos[s*3+2]) * c);
    }
}

// ---------------- update kernel: per 16-node tile ---------------------------
// h += relu([h; agg] @ Wu + bu); pos += dpos / DEG
__global__ void __launch_bounds__(256) upd_kernel(
    const float* __restrict__ Wu, const float* __restrict__ bu)
{
    __shared__ __align__(16) float sm[TE * USTRIDE];   // 32 KB
    int tid = threadIdx.x;
    int n0 = blockIdx.x * TE;

    #pragma unroll 4
    for (int e = 0; e < TE; e++) {
        sm[e*USTRIDE + tid]      = g_h[(n0 + e)*HH + tid];
        sm[e*USTRIDE + HH + tid] = g_agg[(n0 + e)*HH + tid];
    }
    __syncthreads();

    float acc[TE];
    #pragma unroll
    for (int e = 0; e < TE; e++) acc[e] = 0.f;

    const float* wc = Wu + tid;
    for (int k4 = 0; k4 < 128; k4++) {
        float w0 = wc[(4*k4 + 0)*HH];
        float w1 = wc[(4*k4 + 1)*HH];
        float w2 = wc[(4*k4 + 2)*HH];
        float w3 = wc[(4*k4 + 3)*HH];
        #pragma unroll
        for (int e = 0; e < TE; e++) {
            float4 f = *(const float4*)(sm + e*USTRIDE + 4*k4);
            acc[e] = fmaf(f.w, w3, fmaf(f.z, w2, fmaf(f.y, w1, fmaf(f.x, w0, acc[e]))));
        }
    }
    float bj = bu[tid];
    #pragma unroll
    for (int e = 0; e < TE; e++)
        g_h[(n0 + e)*HH + tid] = sm[e*USTRIDE + tid] + fmaxf(acc[e] + bj, 0.f);

    if (tid < TE*SD) {
        int n = n0 + tid / 3, c = tid % 3;
        g_pos[n*3 + c] += g_dpos[n*3 + c] * 0.25f;   // 1/DEG, DEG = E/(B*N) = 4
    }
}

// ---------------- output: out[bn] = h[bn] . W_out + b_out -------------------
__global__ void k_out(const float* __restrict__ Wo, const float* __restrict__ bo,
                      float* __restrict__ out)
{
    int lane = threadIdx.x & 31;
    int node = blockIdx.x * 8 + (threadIdx.x >> 5);
    float v = 0.f;
    #pragma unroll
    for (int r = 0; r < 8; r++) {
        int j = lane + r*32;
        v = fmaf(g_h[node*HH + j], Wo[j], v);
    }
    v += __shfl_xor_sync(0xffffffffu, v, 16);
    v += __shfl_xor_sync(0xffffffffu, v, 8);
    v += __shfl_xor_sync(0xffffffffu, v, 4);
    v += __shfl_xor_sync(0xffffffffu, v, 2);
    v += __shfl_xor_sync(0xffffffffu, v, 1);
    if (lane == 0) out[node] = v + bo[0];
}

// ---------------------------------------------------------------------------
extern "C" void kernel_launch(void* const* d_in, const int* in_sizes, int n_in,
                              void* d_out, int out_size)
{
    const float* x         = (const float*)d_in[0];
    const float* positions = (const float*)d_in[1];
    const float* W_in      = (const float*)d_in[2];
    const float* b_in      = (const float*)d_in[3];
    const float* Wg1       = (const float*)d_in[4];
    const float* bg1       = (const float*)d_in[5];
    const float* Wg2       = (const float*)d_in[6];
    const float* bg2       = (const float*)d_in[7];
    const float* Wm        = (const float*)d_in[8];
    const float* bm        = (const float*)d_in[9];
    const float* Wu        = (const float*)d_in[10];
    const float* bu        = (const float*)d_in[11];
    const float* Wp        = (const float*)d_in[12];
    const float* W_out     = (const float*)d_in[13];
    const float* b_out     = (const float*)d_in[14];
    const int*   edge      = (const int*)d_in[15];
    float* out = (float*)d_out;

    k_h0<<<BB, 256>>>(x, W_in, b_in);
    k_meand<<<NPTS, 256>>>(positions);
    k_geo<<<NPTS, 256>>>(Wg1, bg1, Wg2, bg2);
    k_init<<<NN, 256>>>(positions);

    const int* srcp = edge;
    const int* dstp = edge + NE;
    for (int l = 0; l < LAYERS; l++) {
        const float* Wml = Wm + (size_t)l*513*HH;
        k_zero<<<592, 256>>>();
        pq_kernel<<<NN/TE, 256>>>(Wml);
        edge_kernel<<<NE/TE, 256>>>(srcp, dstp, Wml, bm + l*HH, Wp + l*HH);
        upd_kernel<<<NN/TE, 256>>>(Wu + (size_t)l*512*HH, bu + l*HH);
    }
    k_out<<<NN/8, 256>>>(W_out, b_out, out);
}

// round 6
// speedup vs baseline: 3.4343x; 1.3697x over previous
#include <cuda_runtime.h>
#include <math.h>

#define BB 32
#define FF 128
#define HH 256
#define NPTS 2048
#define SD 3
#define NE 262144
#define NN (BB*NPTS)      // 65536
#define TE 16
#define USTRIDE 512
#define R0 (BB + NPTS)    // 2080 low-rank rows (batch table ++ node table)

// ---------------- scratch (device globals; no allocation allowed) ----------
__device__ float g_h0[BB*HH];
__device__ float g_meand[NPTS];
__device__ float g_g[NPTS*HH];
__device__ float g_h[NN*HH];       // 64 MB
__device__ float g_P[NN*HH];       // 64 MB: H @ Wm_top (layer 1)
__device__ float g_Q[NN*HH];       // 64 MB: H @ Wm_mid (layer 1)
__device__ float g_P0[R0*HH];      // 2 MB: layer-0 low-rank P table
__device__ float g_Q0[R0*HH];      // 2 MB
__device__ float g_U0[R0*HH];      // 2 MB: layer-0 low-rank h@Wu_top table
__device__ float g_pos[NN*SD];
__device__ float g_agg[NN*HH];     // 64 MB
__device__ float g_dpos[NN*SD];

// ---------------- zero agg + dpos -------------------------------------------
__global__ void k_zero()
{
    int i = blockIdx.x * blockDim.x + threadIdx.x;
    int stride = gridDim.x * blockDim.x;
    for (int k = i; k < NN*HH; k += stride) g_agg[k] = 0.f;
    for (int k = i; k < NN*SD; k += stride) g_dpos[k] = 0.f;
}

// ---------------- h0 = x @ W_in + b_in  [32,256] ---------------------------
__global__ void k_h0(const float* __restrict__ x, const float* __restrict__ W,
                     const float* __restrict__ b)
{
    int bi = blockIdx.x, j = threadIdx.x;
    __shared__ float xr[FF];
    if (j < FF) xr[j] = x[bi*FF + j];
    __syncthreads();
    float acc = b[j];
    #pragma unroll 4
    for (int k = 0; k < FF; k++) acc = fmaf(xr[k], W[k*HH + j], acc);
    g_h0[bi*HH + j] = acc;
}

// ---------------- mean pairwise distance per point --------------------------
__global__ void k_meand(const float* __restrict__ P)
{
    int i = blockIdx.x;
    float px = P[i*3+0], py = P[i*3+1], pz = P[i*3+2];
    float s = 0.f;
    for (int j = threadIdx.x; j < NPTS; j += 256) {
        if (j == i) continue;
        float dx = px - P[j*3+0], dy = py - P[j*3+1], dz = pz - P[j*3+2];
        s += sqrtf(dx*dx + dy*dy + dz*dz);
    }
    __shared__ float red[256];
    red[threadIdx.x] = s;
    __syncthreads();
    for (int st = 128; st > 0; st >>= 1) {
        if (threadIdx.x < st) red[threadIdx.x] += red[threadIdx.x + st];
        __syncthreads();
    }
    if (threadIdx.x == 0) g_meand[i] = red[0] / (float)(NPTS - 1);
}

// ------- g = relu(gf@Wg1+bg1)@Wg2+bg2, gf cols are all mean_d ---------------
__global__ void k_geo(const float* __restrict__ Wg1, const float* __restrict__ bg1,
                      const float* __restrict__ Wg2, const float* __restrict__ bg2)
{
    int i = blockIdx.x, j = threadIdx.x;
    __shared__ float t[FF];
    float m = g_meand[i];
    if (j < FF) {
        float ws = Wg1[j] + Wg1[FF + j] + Wg1[2*FF + j];
        t[j] = fmaxf(fmaf(m, ws, bg1[j]), 0.f);
    }
    __syncthreads();
    float acc = bg2[j];
    #pragma unroll 4
    for (int k = 0; k < FF; k++) acc = fmaf(t[k], Wg2[k*HH + j], acc);
    g_g[i*HH + j] = acc;
}

// ---------------- init positions only (h stays low-rank at layer 0) ---------
__global__ void k_posinit(const float* __restrict__ P)
{
    int i = blockIdx.x * blockDim.x + threadIdx.x;  // over NN*SD
    if (i < NN*SD) {
        int bn = i / 3, c = i - bn*3;
        int n = bn & (NPTS - 1);
        g_pos[i] = P[n*3 + c];
    }
}

// ------- layer-0 low-rank tables: rows = [h0 (32) ; g (2048)] ---------------
// P0 = row @ Wm_top, Q0 = row @ Wm_mid, U0 = row @ Wu_top  (one smem tile)
__global__ void __launch_bounds__(256) pq0_kernel(
    const float* __restrict__ Wm, const float* __restrict__ Wu)
{
    __shared__ __align__(16) float sm[TE * HH];   // 16 KB
    int tid = threadIdx.x;
    int r0 = blockIdx.x * TE;

    #pragma unroll 4
    for (int e = 0; e < TE; e++) {
        int r = r0 + e;
        const float* row = (r < BB) ? (g_h0 + r*HH) : (g_g + (r - BB)*HH);
        sm[e*HH + tid] = row[tid];
    }
    __syncthreads();

    float accP[TE], accQ[TE], accU[TE];
    #pragma unroll
    for (int e = 0; e < TE; e++) { accP[e] = 0.f; accQ[e] = 0.f; accU[e] = 0.f; }

    const float* wt = Wm + tid;                 // Wm rows 0..255
    const float* wq = Wm + (size_t)HH*HH + tid; // Wm rows 256..511
    const float* wu = Wu + tid;                 // Wu rows 0..255
    for (int k4 = 0; k4 < HH/4; k4++) {
        float t0 = wt[(4*k4+0)*HH], t1 = wt[(4*k4+1)*HH];
        float t2 = wt[(4*k4+2)*HH], t3 = wt[(4*k4+3)*HH];
        float q0 = wq[(4*k4+0)*HH], q1 = wq[(4*k4+1)*HH];
        float q2 = wq[(4*k4+2)*HH], q3 = wq[(4*k4+3)*HH];
        float u0 = wu[(4*k4+0)*HH], u1 = wu[(4*k4+1)*HH];
        float u2 = wu[(4*k4+2)*HH], u3 = wu[(4*k4+3)*HH];
        #pragma unroll
        for (int e = 0; e < TE; e++) {
            float4 f = *(const float4*)(sm + e*HH + 4*k4);
            accP[e] = fmaf(f.w, t3, fmaf(f.z, t2, fmaf(f.y, t1, fmaf(f.x, t0, accP[e]))));
            accQ[e] = fmaf(f.w, q3, fmaf(f.z, q2, fmaf(f.y, q1, fmaf(f.x, q0, accQ[e]))));
            accU[e] = fmaf(f.w, u3, fmaf(f.z, u2, fmaf(f.y, u1, fmaf(f.x, u0, accU[e]))));
        }
    }
    #pragma unroll
    for (int e = 0; e < TE; e++) {
        g_P0[(r0 + e)*HH + tid] = accP[e];
        g_Q0[(r0 + e)*HH + tid] = accQ[e];
        g_U0[(r0 + e)*HH + tid] = accU[e];
    }
}

// ---------------- layer-0 edgewise: low-rank table gathers ------------------
__global__ void __launch_bounds__(256) edge0_kernel(
    const int* __restrict__ src, const int* __restrict__ dst,
    const float* __restrict__ Wm, const float* __restrict__ bm,
    const float* __restrict__ Wp)
{
    __shared__ int ssrc[TE], sdst[TE];
    __shared__ float sd[TE];
    __shared__ float spart[8][TE];
    int tid = threadIdx.x;
    int e0 = blockIdx.x * TE;

    if (tid < TE) {
        int s = src[e0 + tid], t = dst[e0 + tid];
        ssrc[tid] = s; sdst[tid] = t;
        float dx = g_pos[s*3+0] - g_pos[t*3+0];
        float dy = g_pos[s*3+1] - g_pos[t*3+1];
        float dz = g_pos[s*3+2] - g_pos[t*3+2];
        sd[tid] = sqrtf(dx*dx + dy*dy + dz*dz + 1e-12f);
    }
    __syncthreads();

    float wd = Wm[(size_t)512*HH + tid];
    float bj = bm[tid];
    float wp = Wp[tid];

    float m_[TE];
    #pragma unroll 4
    for (int e = 0; e < TE; e++) {
        int s = ssrc[e], t = sdst[e];
        int bs = s >> 11, ns = s & (NPTS-1);
        int bt = t >> 11, nt = t & (NPTS-1);
        float v = g_P0[bs*HH + tid] + g_P0[(BB + ns)*HH + tid]
                + g_Q0[bt*HH + tid] + g_Q0[(BB + nt)*HH + tid];
        v = fmaf(sd[e], wd, v) + bj;
        m_[e] = fmaxf(v, 0.f);
    }

    #pragma unroll 4
    for (int e = 0; e < TE; e++) atomicAdd(g_agg + sdst[e]*HH + tid, m_[e]);

    int lane = tid & 31, wrp = tid >> 5;
    #pragma unroll
    for (int e = 0; e < TE; e++) {
        float v = m_[e] * wp;
        v += __shfl_xor_sync(0xffffffffu, v, 16);
        v += __shfl_xor_sync(0xffffffffu, v, 8);
        v += __shfl_xor_sync(0xffffffffu, v, 4);
        v += __shfl_xor_sync(0xffffffffu, v, 2);
        v += __shfl_xor_sync(0xffffffffu, v, 1);
        if (lane == 0) spart[wrp][e] = v;
    }
    __syncthreads();
    if (tid < TE) {
        float c = spart[0][tid] + spart[1][tid] + spart[2][tid] + spart[3][tid]
                + spart[4][tid] + spart[5][tid] + spart[6][tid] + spart[7][tid];
        int s = ssrc[tid], t = sdst[tid];
        atomicAdd(g_dpos + t*3+0, (g_pos[t*3+0] - g_pos[s*3+0]) * c);
        atomicAdd(g_dpos + t*3+1, (g_pos[t*3+1] - g_pos[s*3+1]) * c);
        atomicAdd(g_dpos + t*3+2, (g_pos[t*3+2] - g_pos[s*3+2]) * c);
    }
}

// ---------------- layer-0 update: agg@Wu_bot + low-rank h-part --------------
// h1 = (h0[b]+g[n]) + relu(agg@Wu_bot + U0[b] + U0[32+n] + bu); pos += dpos/4
__global__ void __launch_bounds__(256) upd0_kernel(
    const float* __restrict__ Wu, const float* __restrict__ bu)
{
    __shared__ __align__(16) float sm[TE * HH];   // 16 KB (agg tile only)
    int tid = threadIdx.x;
    int n0 = blockIdx.x * TE;

    #pragma unroll 4
    for (int e = 0; e < TE; e++)
        sm[e*HH + tid] = g_agg[(n0 + e)*HH + tid];
    __syncthreads();

    float acc[TE];
    #pragma unroll
    for (int e = 0; e < TE; e++) acc[e] = 0.f;

    const float* wc = Wu + (size_t)HH*HH + tid;   // Wu rows 256..511 (agg part)
    for (int k4 = 0; k4 < HH/4; k4++) {
        float w0 = wc[(4*k4+0)*HH], w1 = wc[(4*k4+1)*HH];
        float w2 = wc[(4*k4+2)*HH], w3 = wc[(4*k4+3)*HH];
        #pragma unroll
        for (int e = 0; e < TE; e++) {
            float4 f = *(const float4*)(sm + e*HH + 4*k4);
            acc[e] = fmaf(f.w, w3, fmaf(f.z, w2, fmaf(f.y, w1, fmaf(f.x, w0, acc[e]))));
        }
    }
    float bj = bu[tid];
    int b = n0 >> 11;                             // same batch for whole tile
    float u0b = g_U0[b*HH + tid];
    float h0b = g_h0[b*HH + tid];
    #pragma unroll
    for (int e = 0; e < TE; e++) {
        int n = (n0 + e) & (NPTS-1);
        float u = acc[e] + u0b + g_U0[(BB + n)*HH + tid] + bj;
        float hold = h0b + g_g[n*HH + tid];
        g_h[(n0 + e)*HH + tid] = hold + fmaxf(u, 0.f);
    }

    if (tid < TE*SD) {
        int n = n0 + tid / 3, c = tid % 3;
        g_pos[n*3 + c] += g_dpos[n*3 + c] * 0.25f;
    }
}

// ---------------- PQ kernel (layer 1): per 16-node tile ---------------------
__global__ void __launch_bounds__(256) pq_kernel(const float* __restrict__ Wm)
{
    __shared__ __align__(16) float sm[TE * HH];   // 16 KB
    int tid = threadIdx.x;
    int n0 = blockIdx.x * TE;

    #pragma unroll 4
    for (int e = 0; e < TE; e++)
        sm[e*HH + tid] = g_h[(n0 + e)*HH + tid];
    __syncthreads();

    float accP[TE], accQ[TE];
    #pragma unroll
    for (int e = 0; e < TE; e++) { accP[e] = 0.f; accQ[e] = 0.f; }

    const float* wt = Wm + tid;
    const float* wq = Wm + (size_t)HH*HH + tid;
    for (int k4 = 0; k4 < HH/4; k4++) {
        float t0 = wt[(4*k4+0)*HH], t1 = wt[(4*k4+1)*HH];
        float t2 = wt[(4*k4+2)*HH], t3 = wt[(4*k4+3)*HH];
        float q0 = wq[(4*k4+0)*HH], q1 = wq[(4*k4+1)*HH];
        float q2 = wq[(4*k4+2)*HH], q3 = wq[(4*k4+3)*HH];
        #pragma unroll
        for (int e = 0; e < TE; e++) {
            float4 f = *(const float4*)(sm + e*HH + 4*k4);
            accP[e] = fmaf(f.w, t3, fmaf(f.z, t2, fmaf(f.y, t1, fmaf(f.x, t0, accP[e]))));
            accQ[e] = fmaf(f.w, q3, fmaf(f.z, q2, fmaf(f.y, q1, fmaf(f.x, q0, accQ[e]))));
        }
    }
    #pragma unroll
    for (int e = 0; e < TE; e++) {
        g_P[(n0 + e)*HH + tid] = accP[e];
        g_Q[(n0 + e)*HH + tid] = accQ[e];
    }
}

// ---------------- edgewise kernel (layer 1) ---------------------------------
__global__ void __launch_bounds__(256) edge_kernel(
    const int* __restrict__ src, const int* __restrict__ dst,
    const float* __restrict__ Wm, const float* __restrict__ bm,
    const float* __restrict__ Wp)
{
    __shared__ int ssrc[TE], sdst[TE];
    __shared__ float sd[TE];
    __shared__ float spart[8][TE];
    int tid = threadIdx.x;
    int e0 = blockIdx.x * TE;

    if (tid < TE) {
        int s = src[e0 + tid], t = dst[e0 + tid];
        ssrc[tid] = s; sdst[tid] = t;
        float dx = g_pos[s*3+0] - g_pos[t*3+0];
        float dy = g_pos[s*3+1] - g_pos[t*3+1];
        float dz = g_pos[s*3+2] - g_pos[t*3+2];
        sd[tid] = sqrtf(dx*dx + dy*dy + dz*dz + 1e-12f);
    }
    __syncthreads();

    float wd = Wm[(size_t)512*HH + tid];
    float bj = bm[tid];
    float wp = Wp[tid];

    float m_[TE];
    #pragma unroll 4
    for (int e = 0; e < TE; e++) {
        float v = g_P[ssrc[e]*HH + tid] + g_Q[sdst[e]*HH + tid];
        v = fmaf(sd[e], wd, v) + bj;
        m_[e] = fmaxf(v, 0.f);
    }

    #pragma unroll 4
    for (int e = 0; e < TE; e++) atomicAdd(g_agg + sdst[e]*HH + tid, m_[e]);

    int lane = tid & 31, wrp = tid >> 5;
    #pragma unroll
    for (int e = 0; e < TE; e++) {
        float v = m_[e] * wp;
        v += __shfl_xor_sync(0xffffffffu, v, 16);
        v += __shfl_xor_sync(0xffffffffu, v, 8);
        v += __shfl_xor_sync(0xffffffffu, v, 4);
        v += __shfl_xor_sync(0xffffffffu, v, 2);
        v += __shfl_xor_sync(0xffffffffu, v, 1);
        if (lane == 0) spart[wrp][e] = v;
    }
    __syncthreads();
    if (tid < TE) {
        float c = spart[0][tid] + spart[1][tid] + spart[2][tid] + spart[3][tid]
                + spart[4][tid] + spart[5][tid] + spart[6][tid] + spart[7][tid];
        int s = ssrc[tid], t = sdst[tid];
        atomicAdd(g_dpos + t*3+0, (g_pos[t*3+0] - g_pos[s*3+0]) * c);
        atomicAdd(g_dpos + t*3+1, (g_pos[t*3+1] - g_pos[s*3+1]) * c);
        atomicAdd(g_dpos + t*3+2, (g_pos[t*3+2] - g_pos[s*3+2]) * c);
    }
}

// ---------------- update kernel (layer 1): full 512-K GEMM ------------------
__global__ void __launch_bounds__(256) upd_kernel(
    const float* __restrict__ Wu, const float* __restrict__ bu)
{
    __shared__ __align__(16) float sm[TE * USTRIDE];   // 32 KB
    int tid = threadIdx.x;
    int n0 = blockIdx.x * TE;

    #pragma unroll 4
    for (int e = 0; e < TE; e++) {
        sm[e*USTRIDE + tid]      = g_h[(n0 + e)*HH + tid];
        sm[e*USTRIDE + HH + tid] = g_agg[(n0 + e)*HH + tid];
    }
    __syncthreads();

    float acc[TE];
    #pragma unroll
    for (int e = 0; e < TE; e++) acc[e] = 0.f;

    const float* wc = Wu + tid;
    for (int k4 = 0; k4 < 128; k4++) {
        float w0 = wc[(4*k4+0)*HH], w1 = wc[(4*k4+1)*HH];
        float w2 = wc[(4*k4+2)*HH], w3 = wc[(4*k4+3)*HH];
        #pragma unroll
        for (int e = 0; e < TE; e++) {
            float4 f = *(const float4*)(sm + e*USTRIDE + 4*k4);
            acc[e] = fmaf(f.w, w3, fmaf(f.z, w2, fmaf(f.y, w1, fmaf(f.x, w0, acc[e]))));
        }
    }
    float bj = bu[tid];
    #pragma unroll
    for (int e = 0; e < TE; e++)
        g_h[(n0 + e)*HH + tid] = sm[e*USTRIDE + tid] + fmaxf(acc[e] + bj, 0.f);

    if (tid < TE*SD) {
        int n = n0 + tid / 3, c = tid % 3;
        g_pos[n*3 + c] += g_dpos[n*3 + c] * 0.25f;
    }
}

// ---------------- output: out[bn] = h[bn] . W_out + b_out -------------------
__global__ void k_out(const float* __restrict__ Wo, const float* __restrict__ bo,
                      float* __restrict__ out)
{
    int lane = threadIdx.x & 31;
    int node = blockIdx.x * 8 + (threadIdx.x >> 5);
    float v = 0.f;
    #pragma unroll
    for (int r = 0; r < 8; r++) {
        int j = lane + r*32;
        v = fmaf(g_h[node*HH + j], Wo[j], v);
    }
    v += __shfl_xor_sync(0xffffffffu, v, 16);
    v += __shfl_xor_sync(0xffffffffu, v, 8);
    v += __shfl_xor_sync(0xffffffffu, v, 4);
    v += __shfl_xor_sync(0xffffffffu, v, 2);
    v += __shfl_xor_sync(0xffffffffu, v, 1);
    if (lane == 0) out[node] = v + bo[0];
}

// ---------------------------------------------------------------------------
extern "C" void kernel_launch(void* const* d_in, const int* in_sizes, int n_in,
                              void* d_out, int out_size)
{
    const float* x         = (const float*)d_in[0];
    const float* positions = (const float*)d_in[1];
    const float* W_in      = (const float*)d_in[2];
    const float* b_in      = (const float*)d_in[3];
    const float* Wg1       = (const float*)d_in[4];
    const float* bg1       = (const float*)d_in[5];
    const float* Wg2       = (const float*)d_in[6];
    const float* bg2       = (const float*)d_in[7];
    const float* Wm        = (const float*)d_in[8];
    const float* bm        = (const float*)d_in[9];
    const float* Wu        = (const float*)d_in[10];
    const float* bu        = (const float*)d_in[11];
    const float* Wp        = (const float*)d_in[12];
    const float* W_out     = (const float*)d_in[13];
    const float* b_out     = (const float*)d_in[14];
    const int*   edge      = (const int*)d_in[15];
    float* out = (float*)d_out;

    const int* srcp = edge;
    const int* dstp = edge + NE;

    k_h0<<<BB, 256>>>(x, W_in, b_in);
    k_meand<<<NPTS, 256>>>(positions);
    k_geo<<<NPTS, 256>>>(Wg1, bg1, Wg2, bg2);
    k_posinit<<<(NN*SD + 255)/256, 256>>>(positions);

    // ---- layer 0 (low-rank h) ----
    k_zero<<<592, 256>>>();
    pq0_kernel<<<R0/TE, 256>>>(Wm, Wu);
    edge0_kernel<<<NE/TE, 256>>>(srcp, dstp, Wm, bm, Wp);
    upd0_kernel<<<NN/TE, 256>>>(Wu, bu);

    // ---- layer 1 (full rank) ----
    const float* Wm1 = Wm + (size_t)513*HH;
    k_zero<<<592, 256>>>();
    pq_kernel<<<NN/TE, 256>>>(Wm1);
    edge_kernel<<<NE/TE, 256>>>(srcp, dstp, Wm1, bm + HH, Wp + HH);
    upd_kernel<<<NN/TE, 256>>>(Wu + (size_t)512*HH, bu + HH);

    k_out<<<NN/8, 256>>>(W_out, b_out, out);
}

// round 7
// speedup vs baseline: 4.4288x; 1.2896x over previous
#include <cuda_runtime.h>
#include <cuda_bf16.h>
#include <math.h>

#define BB 32
#define FF 128
#define HH 256
#define NPTS 2048
#define SD 3
#define NE 262144
#define NN (BB*NPTS)      // 65536
#define TE 16
#define R0 (BB + NPTS)    // 2080 low-rank rows

// GEMM tiling
#define BM 128
#define BN 64
#define BK 32
#define KPAD 40

// ---------------- scratch (device globals; no allocation allowed) ----------
__device__ float g_h0[BB*HH];
__device__ float g_meand[NPTS];
__device__ float g_g[NPTS*HH];
__device__ float g_h[NN*HH];        // 64 MB  (h after layer 0)
__device__ float g_h2[NN*HH];       // 64 MB  (h after layer 1)
__device__ float g_PQ[(size_t)NN*512]; // 128 MB: [P | Q] for layer 1
__device__ float g_P0[R0*HH];       // layer-0 low-rank tables
__device__ float g_Q0[R0*HH];
__device__ float g_U0[R0*HH];
__device__ float g_pos[NN*SD];
__device__ float g_agg[NN*HH];      // 64 MB
__device__ float g_dpos[NN*SD];

// pre-split transposed weights (bf16 hi/lo), layout [N][K]
__device__ __nv_bfloat16 g_Bpq_hi[512*256], g_Bpq_lo[512*256];   // pq1: K=256,N=512
__device__ __nv_bfloat16 g_Bu1_hi[256*512], g_Bu1_lo[256*512];   // upd1: K=512,N=256
__device__ __nv_bfloat16 g_Bu0_hi[256*256], g_Bu0_lo[256*256];   // upd0: K=256,N=256

// ---------------- helpers ----------------------------------------------------
__device__ __forceinline__ unsigned pack_bf2(__nv_bfloat16 a, __nv_bfloat16 b) {
    return (unsigned)__bfloat16_as_ushort(a) | ((unsigned)__bfloat16_as_ushort(b) << 16);
}
__device__ __forceinline__ void split2(float x, float y, unsigned& hi, unsigned& lo) {
    __nv_bfloat16 hx = __float2bfloat16(x), hy = __float2bfloat16(y);
    float rx = x - __bfloat162float(hx);
    float ry = y - __bfloat162float(hy);
    hi = pack_bf2(hx, hy);
    lo = pack_bf2(__float2bfloat16(rx), __float2bfloat16(ry));
}
__device__ __forceinline__ void mma16816(float* c, unsigned a0, unsigned a1,
                                         unsigned a2, unsigned a3,
                                         unsigned b0, unsigned b1) {
    asm volatile(
        "mma.sync.aligned.m16n8k16.row.col.f32.bf16.bf16.f32 "
        "{%0,%1,%2,%3}, {%4,%5,%6,%7}, {%8,%9}, {%0,%1,%2,%3};\n"
        : "+f"(c[0]), "+f"(c[1]), "+f"(c[2]), "+f"(c[3])
        : "r"(a0), "r"(a1), "r"(a2), "r"(a3), "r"(b0), "r"(b1));
}

// shared GEMM mainloop: C[128x64] tile, A fp32 (two segments along K), B pre-split bf16
__device__ __forceinline__ void gemm_tile(
    const float* __restrict__ Aseg0, const float* __restrict__ Aseg1, int kSplit,
    int Ktot,
    const __nv_bfloat16* __restrict__ BThi, const __nv_bfloat16* __restrict__ BTlo,
    int m0, int n0,
    __nv_bfloat16* sAh, __nv_bfloat16* sAl, __nv_bfloat16* sBh, __nv_bfloat16* sBl,
    float acc[2][4][4])
{
    int tid  = threadIdx.x;
    int lane = tid & 31, warp = tid >> 5;
    int g = lane >> 2, tg = lane & 3;
    int wM = warp >> 1, wN = warp & 1;

    for (int k0 = 0; k0 < Ktot; k0 += BK) {
        // A tile (128 x 32 fp32) -> split bf16 hi/lo to smem
        const float* As; int acol;
        if (k0 < kSplit) { As = Aseg0; acol = k0; }
        else             { As = Aseg1; acol = k0 - kSplit; }
        for (int i = tid; i < BM*8; i += 256) {
            int row = i >> 3, c4 = (i & 7) * 4;
            float4 f = *(const float4*)(As + (size_t)(m0 + row)*HH + acol + c4);
            unsigned h01, l01, h23, l23;
            split2(f.x, f.y, h01, l01);
            split2(f.z, f.w, h23, l23);
            int so = row*KPAD + c4;
            *(unsigned*)(sAh + so)     = h01;
            *(unsigned*)(sAh + so + 2) = h23;
            *(unsigned*)(sAl + so)     = l01;
            *(unsigned*)(sAl + so + 2) = l23;
        }
        // B tile (64 x 32 bf16 hi/lo), global layout [N][Ktot]
        for (int i = tid; i < BN*16; i += 256) {
            int n = i >> 4, kc = (i & 15) * 2;
            size_t go = (size_t)(n0 + n)*Ktot + k0 + kc;
            *(unsigned*)(sBh + n*KPAD + kc) = *(const unsigned*)(BThi + go);
            *(unsigned*)(sBl + n*KPAD + kc) = *(const unsigned*)(BTlo + go);
        }
        __syncthreads();

        #pragma unroll
        for (int ks = 0; ks < BK; ks += 16) {
            unsigned ah[2][4], al[2][4];
            #pragma unroll
            for (int fm = 0; fm < 2; fm++) {
                int base = (wM*32 + fm*16 + g)*KPAD + ks + tg*2;
                ah[fm][0] = *(unsigned*)(sAh + base);
                ah[fm][1] = *(unsigned*)(sAh + base + 8*KPAD);
                ah[fm][2] = *(unsigned*)(sAh + base + 8);
                ah[fm][3] = *(unsigned*)(sAh + base + 8*KPAD + 8);
                al[fm][0] = *(unsigned*)(sAl + base);
                al[fm][1] = *(unsigned*)(sAl + base + 8*KPAD);
                al[fm][2] = *(unsigned*)(sAl + base + 8);
                al[fm][3] = *(unsigned*)(sAl + base + 8*KPAD + 8);
            }
            #pragma unroll
            for (int fn = 0; fn < 4; fn++) {
                int bb = (wN*32 + fn*8 + g)*KPAD + ks + tg*2;
                unsigned bh0 = *(unsigned*)(sBh + bb), bh1 = *(unsigned*)(sBh + bb + 8);
                unsigned bl0 = *(unsigned*)(sBl + bb), bl1 = *(unsigned*)(sBl + bb + 8);
                #pragma unroll
                for (int fm = 0; fm < 2; fm++) {
                    mma16816(acc[fm][fn], ah[fm][0], ah[fm][1], ah[fm][2], ah[fm][3], bh0, bh1);
                    mma16816(acc[fm][fn], ah[fm][0], ah[fm][1], ah[fm][2], ah[fm][3], bl0, bl1);
                    mma16816(acc[fm][fn], al[fm][0], al[fm][1], al[fm][2], al[fm][3], bh0, bh1);
                }
            }
        }
        __syncthreads();
    }
}

// ---------------- weight prep kernels (split + transpose to [N][K]) ---------
__global__ void k_prep_pq(const float* __restrict__ Wm1)   // B'[k][n]: n<256 top, else mid
{
    int idx = blockIdx.x*256 + threadIdx.x;   // over 256*512
    int k = idx >> 9, n = idx & 511;
    float v = (n < 256) ? Wm1[k*HH + n] : Wm1[(256 + k)*HH + (n - 256)];
    __nv_bfloat16 h = __float2bfloat16(v);
    g_Bpq_hi[n*256 + k] = h;
    g_Bpq_lo[n*256 + k] = __float2bfloat16(v - __bfloat162float(h));
}
__global__ void k_prep_u1(const float* __restrict__ Wu1)   // [512][256] -> [256][512]
{
    int idx = blockIdx.x*256 + threadIdx.x;   // over 512*256
    int k = idx >> 8, n = idx & 255;
    float v = Wu1[k*HH + n];
    __nv_bfloat16 h = __float2bfloat16(v);
    g_Bu1_hi[n*512 + k] = h;
    g_Bu1_lo[n*512 + k] = __float2bfloat16(v - __bfloat162float(h));
}
__global__ void k_prep_u0(const float* __restrict__ Wu0)   // rows 256..511 -> [256][256]
{
    int idx = blockIdx.x*256 + threadIdx.x;   // over 256*256
    int k = idx >> 8, n = idx & 255;
    float v = Wu0[(256 + k)*HH + n];
    __nv_bfloat16 h = __float2bfloat16(v);
    g_Bu0_hi[n*256 + k] = h;
    g_Bu0_lo[n*256 + k] = __float2bfloat16(v - __bfloat162float(h));
}

// ---------------- zero agg + dpos -------------------------------------------
__global__ void k_zero()
{
    int i = blockIdx.x * blockDim.x + threadIdx.x;
    int stride = gridDim.x * blockDim.x;
    for (int k = i; k < NN*HH; k += stride) g_agg[k] = 0.f;
    for (int k = i; k < NN*SD; k += stride) g_dpos[k] = 0.f;
}

// ---------------- small front-end kernels ------------------------------------
__global__ void k_h0(const float* __restrict__ x, const float* __restrict__ W,
                     const float* __restrict__ b)
{
    int bi = blockIdx.x, j = threadIdx.x;
    __shared__ float xr[FF];
    if (j < FF) xr[j] = x[bi*FF + j];
    __syncthreads();
    float acc = b[j];
    #pragma unroll 4
    for (int k = 0; k < FF; k++) acc = fmaf(xr[k], W[k*HH + j], acc);
    g_h0[bi*HH + j] = acc;
}

__global__ void k_meand(const float* __restrict__ P)
{
    int i = blockIdx.x;
    float px = P[i*3+0], py = P[i*3+1], pz = P[i*3+2];
    float s = 0.f;
    for (int j = threadIdx.x; j < NPTS; j += 256) {
        if (j == i) continue;
        float dx = px - P[j*3+0], dy = py - P[j*3+1], dz = pz - P[j*3+2];
        s += sqrtf(dx*dx + dy*dy + dz*dz);
    }
    __shared__ float red[256];
    red[threadIdx.x] = s;
    __syncthreads();
    for (int st = 128; st > 0; st >>= 1) {
        if (threadIdx.x < st) red[threadIdx.x] += red[threadIdx.x + st];
        __syncthreads();
    }
    if (threadIdx.x == 0) g_meand[i] = red[0] / (float)(NPTS - 1);
}

__global__ void k_geo(const float* __restrict__ Wg1, const float* __restrict__ bg1,
                      const float* __restrict__ Wg2, const float* __restrict__ bg2)
{
    int i = blockIdx.x, j = threadIdx.x;
    __shared__ float t[FF];
    float m = g_meand[i];
    if (j < FF) {
        float ws = Wg1[j] + Wg1[FF + j] + Wg1[2*FF + j];
        t[j] = fmaxf(fmaf(m, ws, bg1[j]), 0.f);
    }
    __syncthreads();
    float acc = bg2[j];
    #pragma unroll 4
    for (int k = 0; k < FF; k++) acc = fmaf(t[k], Wg2[k*HH + j], acc);
    g_g[i*HH + j] = acc;
}

__global__ void k_posinit(const float* __restrict__ P)
{
    int i = blockIdx.x * blockDim.x + threadIdx.x;
    if (i < NN*SD) {
        int bn = i / 3, c = i - bn*3;
        int n = bn & (NPTS - 1);
        g_pos[i] = P[n*3 + c];
    }
}

__global__ void k_posupd()
{
    int i = blockIdx.x * blockDim.x + threadIdx.x;
    if (i < NN*SD) g_pos[i] += g_dpos[i] * 0.25f;   // 1/DEG, DEG = 4
}

// ------- layer-0 low-rank tables: rows = [h0 (32) ; g (2048)] ---------------
__global__ void __launch_bounds__(256) pq0_kernel(
    const float* __restrict__ Wm, const float* __restrict__ Wu)
{
    __shared__ __align__(16) float sm[TE * HH];
    int tid = threadIdx.x;
    int r0 = blockIdx.x * TE;

    #pragma unroll 4
    for (int e = 0; e < TE; e++) {
        int r = r0 + e;
        const float* row = (r < BB) ? (g_h0 + r*HH) : (g_g + (r - BB)*HH);
        sm[e*HH + tid] = row[tid];
    }
    __syncthreads();

    float accP[TE], accQ[TE], accU[TE];
    #pragma unroll
    for (int e = 0; e < TE; e++) { accP[e] = 0.f; accQ[e] = 0.f; accU[e] = 0.f; }

    const float* wt = Wm + tid;
    const float* wq = Wm + (size_t)HH*HH + tid;
    const float* wu = Wu + tid;
    for (int k4 = 0; k4 < HH/4; k4++) {
        float t0 = wt[(4*k4+0)*HH], t1 = wt[(4*k4+1)*HH];
        float t2 = wt[(4*k4+2)*HH], t3 = wt[(4*k4+3)*HH];
        float q0 = wq[(4*k4+0)*HH], q1 = wq[(4*k4+1)*HH];
        float q2 = wq[(4*k4+2)*HH], q3 = wq[(4*k4+3)*HH];
        float u0 = wu[(4*k4+0)*HH], u1 = wu[(4*k4+1)*HH];
        float u2 = wu[(4*k4+2)*HH], u3 = wu[(4*k4+3)*HH];
        #pragma unroll
        for (int e = 0; e < TE; e++) {
            float4 f = *(const float4*)(sm + e*HH + 4*k4);
            accP[e] = fmaf(f.w, t3, fmaf(f.z, t2, fmaf(f.y, t1, fmaf(f.x, t0, accP[e]))));
            accQ[e] = fmaf(f.w, q3, fmaf(f.z, q2, fmaf(f.y, q1, fmaf(f.x, q0, accQ[e]))));
            accU[e] = fmaf(f.w, u3, fmaf(f.z, u2, fmaf(f.y, u1, fmaf(f.x, u0, accU[e]))));
        }
    }
    #pragma unroll
    for (int e = 0; e < TE; e++) {
        g_P0[(r0 + e)*HH + tid] = accP[e];
        g_Q0[(r0 + e)*HH + tid] = accQ[e];
        g_U0[(r0 + e)*HH + tid] = accU[e];
    }
}

// ---------------- layer-0 edgewise (with dpos; low-rank tables) -------------
__global__ void __launch_bounds__(256) edge0_kernel(
    const int* __restrict__ src, const int* __restrict__ dst,
    const float* __restrict__ Wm, const float* __restrict__ bm,
    const float* __restrict__ Wp)
{
    __shared__ int ssrc[TE], sdst[TE];
    __shared__ float sd[TE];
    __shared__ float spart[8][TE];
    int tid = threadIdx.x;
    int e0 = blockIdx.x * TE;

    if (tid < TE) {
        int s = src[e0 + tid], t = dst[e0 + tid];
        ssrc[tid] = s; sdst[tid] = t;
        float dx = g_pos[s*3+0] - g_pos[t*3+0];
        float dy = g_pos[s*3+1] - g_pos[t*3+1];
        float dz = g_pos[s*3+2] - g_pos[t*3+2];
        sd[tid] = sqrtf(dx*dx + dy*dy + dz*dz + 1e-12f);
    }
    __syncthreads();

    float wd = Wm[(size_t)512*HH + tid];
    float bj = bm[tid];
    float wp = Wp[tid];

    float m_[TE];
    #pragma unroll 4
    for (int e = 0; e < TE; e++) {
        int s = ssrc[e], t = sdst[e];
        int bs = s >> 11, ns = s & (NPTS-1);
        int bt = t >> 11, nt = t & (NPTS-1);
        float v = g_P0[bs*HH + tid] + g_P0[(BB + ns)*HH + tid]
                + g_Q0[bt*HH + tid] + g_Q0[(BB + nt)*HH + tid];
        v = fmaf(sd[e], wd, v) + bj;
        m_[e] = fmaxf(v, 0.f);
    }

    #pragma unroll 4
    for (int e = 0; e < TE; e++) atomicAdd(g_agg + sdst[e]*HH + tid, m_[e]);

    int lane = tid & 31, wrp = tid >> 5;
    #pragma unroll
    for (int e = 0; e < TE; e++) {
        float v = m_[e] * wp;
        v += __shfl_xor_sync(0xffffffffu, v, 16);
        v += __shfl_xor_sync(0xffffffffu, v, 8);
        v += __shfl_xor_sync(0xffffffffu, v, 4);
        v += __shfl_xor_sync(0xffffffffu, v, 2);
        v += __shfl_xor_sync(0xffffffffu, v, 1);
        if (lane == 0) spart[wrp][e] = v;
    }
    __syncthreads();
    if (tid < TE) {
        float c = spart[0][tid] + spart[1][tid] + spart[2][tid] + spart[3][tid]
                + spart[4][tid] + spart[5][tid] + spart[6][tid] + spart[7][tid];
        int s = ssrc[tid], t = sdst[tid];
        atomicAdd(g_dpos + t*3+0, (g_pos[t*3+0] - g_pos[s*3+0]) * c);
        atomicAdd(g_dpos + t*3+1, (g_pos[t*3+1] - g_pos[s*3+1]) * c);
        atomicAdd(g_dpos + t*3+2, (g_pos[t*3+2] - g_pos[s*3+2]) * c);
    }
}

// ---------------- upd0 (MMA): h = h0[b]+g[n] + relu(agg@Wu_bot + U0 + bu) ---
__global__ void __launch_bounds__(256) upd0_mma(const float* __restrict__ bu)
{
    __shared__ __align__(16) __nv_bfloat16 sAh[BM*KPAD], sAl[BM*KPAD];
    __shared__ __align__(16) __nv_bfloat16 sBh[BN*KPAD], sBl[BN*KPAD];
    float acc[2][4][4];
    #pragma unroll
    for (int a = 0; a < 2; a++)
        #pragma unroll
        for (int b = 0; b < 4; b++)
            #pragma unroll
            for (int c = 0; c < 4; c++) acc[a][b][c] = 0.f;

    int m0 = blockIdx.x * BM;
    int n0 = blockIdx.y * BN;
    gemm_tile(g_agg, g_agg, HH, HH, g_Bu0_hi, g_Bu0_lo, m0, n0, sAh, sAl, sBh, sBl, acc);

    int lane = threadIdx.x & 31, warp = threadIdx.x >> 5;
    int g = lane >> 2, tg = lane & 3;
    int wM = warp >> 1, wN = warp & 1;
    int b = m0 >> 11;                       // whole block is one batch (BM | 2048)
    #pragma unroll
    for (int fm = 0; fm < 2; fm++) {
        #pragma unroll
        for (int fn = 0; fn < 4; fn++) {
            int c = n0 + wN*32 + fn*8 + tg*2;
            float b0 = bu[c], b1 = bu[c+1];
            #pragma unroll
            for (int rr = 0; rr < 2; rr++) {
                int m = m0 + wM*32 + fm*16 + g + rr*8;
                int n = m & (NPTS-1);
                float u0a = g_U0[b*HH + c]        + bu[0]*0.f;  // keep simple
                float base0 = g_h0[b*HH + c]   + g_g[n*HH + c];
                float base1 = g_h0[b*HH + c+1] + g_g[n*HH + c+1];
                float ua0 = acc[fm][fn][rr*2+0] + g_U0[b*HH + c]   + g_U0[(BB+n)*HH + c]   + b0;
                float ua1 = acc[fm][fn][rr*2+1] + g_U0[b*HH + c+1] + g_U0[(BB+n)*HH + c+1] + b1;
                (void)u0a;
                float2 o;
                o.x = base0 + fmaxf(ua0, 0.f);
                o.y = base1 + fmaxf(ua1, 0.f);
                *(float2*)(g_h + (size_t)m*HH + c) = o;
            }
        }
    }
}

// ---------------- pq1 (MMA): g_PQ = h @ [Wm_top | Wm_mid] -------------------
__global__ void __launch_bounds__(256) pq1_mma()
{
    __shared__ __align__(16) __nv_bfloat16 sAh[BM*KPAD], sAl[BM*KPAD];
    __shared__ __align__(16) __nv_bfloat16 sBh[BN*KPAD], sBl[BN*KPAD];
    float acc[2][4][4];
    #pragma unroll
    for (int a = 0; a < 2; a++)
        #pragma unroll
        for (int b = 0; b < 4; b++)
            #pragma unroll
            for (int c = 0; c < 4; c++) acc[a][b][c] = 0.f;

    int m0 = blockIdx.x * BM;
    int n0 = blockIdx.y * BN;
    gemm_tile(g_h, g_h, HH, HH, g_Bpq_hi, g_Bpq_lo, m0, n0, sAh, sAl, sBh, sBl, acc);

    int lane = threadIdx.x & 31, warp = threadIdx.x >> 5;
    int g = lane >> 2, tg = lane & 3;
    int wM = warp >> 1, wN = warp & 1;
    #pragma unroll
    for (int fm = 0; fm < 2; fm++) {
        #pragma unroll
        for (int fn = 0; fn < 4; fn++) {
            int c = n0 + wN*32 + fn*8 + tg*2;
            #pragma unroll
            for (int rr = 0; rr < 2; rr++) {
                int m = m0 + wM*32 + fm*16 + g + rr*8;
                float2 o; o.x = acc[fm][fn][rr*2+0]; o.y = acc[fm][fn][rr*2+1];
                *(float2*)(g_PQ + (size_t)m*512 + c) = o;
            }
        }
    }
}

// ---------------- layer-1 edgewise (no dpos — dead after last layer) --------
__global__ void __launch_bounds__(256) edge1_kernel(
    const int* __restrict__ src, const int* __restrict__ dst,
    const float* __restrict__ Wm, const float* __restrict__ bm)
{
    __shared__ int ssrc[TE], sdst[TE];
    __shared__ float sd[TE];
    int tid = threadIdx.x;
    int e0 = blockIdx.x * TE;

    if (tid < TE) {
        int s = src[e0 + tid], t = dst[e0 + tid];
        ssrc[tid] = s; sdst[tid] = t;
        float dx = g_pos[s*3+0] - g_pos[t*3+0];
        float dy = g_pos[s*3+1] - g_pos[t*3+1];
        float dz = g_pos[s*3+2] - g_pos[t*3+2];
        sd[tid] = sqrtf(dx*dx + dy*dy + dz*dz + 1e-12f);
    }
    __syncthreads();

    float wd = Wm[(size_t)512*HH + tid];
    float bj = bm[tid];

    #pragma unroll 4
    for (int e = 0; e < TE; e++) {
        float v = g_PQ[(size_t)ssrc[e]*512 + tid] + g_PQ[(size_t)sdst[e]*512 + 256 + tid];
        v = fmaf(sd[e], wd, v) + bj;
        atomicAdd(g_agg + sdst[e]*HH + tid, fmaxf(v, 0.f));
    }
}

// ---------------- upd1 (MMA): g_h2 = h + relu([h;agg]@Wu + bu) --------------
__global__ void __launch_bounds__(256) upd1_mma(const float* __restrict__ bu)
{
    __shared__ __align__(16) __nv_bfloat16 sAh[BM*KPAD], sAl[BM*KPAD];
    __shared__ __align__(16) __nv_bfloat16 sBh[BN*KPAD], sBl[BN*KPAD];
    float acc[2][4][4];
    #pragma unroll
    for (int a = 0; a < 2; a++)
        #pragma unroll
        for (int b = 0; b < 4; b++)
            #pragma unroll
            for (int c = 0; c < 4; c++) acc[a][b][c] = 0.f;

    int m0 = blockIdx.x * BM;
    int n0 = blockIdx.y * BN;
    gemm_tile(g_h, g_agg, HH, 2*HH, g_Bu1_hi, g_Bu1_lo, m0, n0, sAh, sAl, sBh, sBl, acc);

    int lane = threadIdx.x & 31, warp = threadIdx.x >> 5;
    int g = lane >> 2, tg = lane & 3;
    int wM = warp >> 1, wN = warp & 1;
    #pragma unroll
    for (int fm = 0; fm < 2; fm++) {
        #pragma unroll
        for (int fn = 0; fn < 4; fn++) {
            int c = n0 + wN*32 + fn*8 + tg*2;
            float b0 = bu[c], b1 = bu[c+1];
            #pragma unroll
            for (int rr = 0; rr < 2; rr++) {
                int m = m0 + wM*32 + fm*16 + g + rr*8;
                float2 hold = *(const float2*)(g_h + (size_t)m*HH + c);
                float2 o;
                o.x = hold.x + fmaxf(acc[fm][fn][rr*2+0] + b0, 0.f);
                o.y = hold.y + fmaxf(acc[fm][fn][rr*2+1] + b1, 0.f);
                *(float2*)(g_h2 + (size_t)m*HH + c) = o;
            }
        }
    }
}

// ---------------- output: out[bn] = h2[bn] . W_out + b_out ------------------
__global__ void k_out(const float* __restrict__ Wo, const float* __restrict__ bo,
                      float* __restrict__ out)
{
    int lane = threadIdx.x & 31;
    int node = blockIdx.x * 8 + (threadIdx.x >> 5);
    float v = 0.f;
    #pragma unroll
    for (int r = 0; r < 8; r++) {
        int j = lane + r*32;
        v = fmaf(g_h2[node*HH + j], Wo[j], v);
    }
    v += __shfl_xor_sync(0xffffffffu, v, 16);
    v += __shfl_xor_sync(0xffffffffu, v, 8);
    v += __shfl_xor_sync(0xffffffffu, v, 4);
    v += __shfl_xor_sync(0xffffffffu, v, 2);
    v += __shfl_xor_sync(0xffffffffu, v, 1);
    if (lane == 0) out[node] = v + bo[0];
}

// ---------------------------------------------------------------------------
extern "C" void kernel_launch(void* const* d_in, const int* in_sizes, int n_in,
                              void* d_out, int out_size)
{
    const float* x         = (const float*)d_in[0];
    const float* positions = (const float*)d_in[1];
    const float* W_in      = (const float*)d_in[2];
    const float* b_in      = (const float*)d_in[3];
    const float* Wg1       = (const float*)d_in[4];
    const float* bg1       = (const float*)d_in[5];
    const float* Wg2       = (const float*)d_in[6];
    const float* bg2       = (const float*)d_in[7];
    const float* Wm        = (const float*)d_in[8];
    const float* bm        = (const float*)d_in[9];
    const float* Wu        = (const float*)d_in[10];
    const float* bu        = (const float*)d_in[11];
    const float* Wp        = (const float*)d_in[12];
    const float* W_out     = (const float*)d_in[13];
    const float* b_out     = (const float*)d_in[14];
    const int*   edge      = (const int*)d_in[15];
    float* out = (float*)d_out;

    const int* srcp = edge;
    const int* dstp = edge + NE;
    const float* Wm1 = Wm + (size_t)513*HH;
    const float* Wu1 = Wu + (size_t)512*HH;

    // front-end + weight prep
    k_h0<<<BB, 256>>>(x, W_in, b_in);
    k_meand<<<NPTS, 256>>>(positions);
    k_geo<<<NPTS, 256>>>(Wg1, bg1, Wg2, bg2);
    k_posinit<<<(NN*SD + 255)/256, 256>>>(positions);
    k_prep_pq<<<512, 256>>>(Wm1);
    k_prep_u1<<<512, 256>>>(Wu1);
    k_prep_u0<<<256, 256>>>(Wu);

    // ---- layer 0 (low-rank h) ----
    k_zero<<<592, 256>>>();
    pq0_kernel<<<R0/TE, 256>>>(Wm, Wu);
    edge0_kernel<<<NE/TE, 256>>>(srcp, dstp, Wm, bm, Wp);
    upd0_mma<<<dim3(NN/BM, HH/BN), 256>>>(bu);
    k_posupd<<<(NN*SD + 255)/256, 256>>>();

    // ---- layer 1 (full rank, tensor-core GEMMs) ----
    k_zero<<<592, 256>>>();
    pq1_mma<<<dim3(NN/BM, 512/BN), 256>>>();
    edge1_kernel<<<NE/TE, 256>>>(srcp, dstp, Wm1, bm + HH);
    upd1_mma<<<dim3(NN/BM, HH/BN), 256>>>(bu + HH);

    k_out<<<NN/8, 256>>>(W_out, b_out, out);
}

// round 8
// speedup vs baseline: 4.5974x; 1.0381x over previous
#include <cuda_runtime.h>
#include <cuda_bf16.h>
#include <math.h>

#define BB 32
#define FF 128
#define HH 256
#define NPTS 2048
#define SD 3
#define NE 262144
#define NN (BB*NPTS)      // 65536
#define TE 16
#define R0 (BB + NPTS)

// GEMM tiling
#define BM 128
#define BN 64
#define BK 32
#define KPAD 40

// ---------------- scratch (device globals; no allocation allowed) ----------
__device__ float g_h0[BB*HH];
__device__ float g_meand[NPTS];
__device__ float g_g[NPTS*HH];
__device__ float g_PQ[(size_t)NN*512];      // 128 MB: [P | Q] layer 1
__device__ float g_P0[R0*HH];
__device__ float g_Q0[R0*HH];
__device__ float g_U0[R0*HH];
__device__ float g_pos[NN*SD];
__device__ float g_agg[NN*HH];              // 64 MB (fp32 atomic target)
__device__ float g_dpos[NN*SD];

// bf16 hi/lo activations (A operands)
__device__ __nv_bfloat16 g_h_hi[NN*HH], g_h_lo[NN*HH];       // 32+32 MB
__device__ __nv_bfloat16 g_agg_hi[NN*HH], g_agg_lo[NN*HH];   // 32+32 MB

// pre-split transposed weights (bf16 hi/lo), layout [N][K]
__device__ __nv_bfloat16 g_Bpq_hi[512*256], g_Bpq_lo[512*256];
__device__ __nv_bfloat16 g_Bu1_hi[256*512], g_Bu1_lo[256*512];
__device__ __nv_bfloat16 g_Bu0_hi[256*256], g_Bu0_lo[256*256];

// ---------------- helpers ----------------------------------------------------
__device__ __forceinline__ unsigned pack_bf2(__nv_bfloat16 a, __nv_bfloat16 b) {
    return (unsigned)__bfloat16_as_ushort(a) | ((unsigned)__bfloat16_as_ushort(b) << 16);
}
__device__ __forceinline__ void mma16816(float* c, unsigned a0, unsigned a1,
                                         unsigned a2, unsigned a3,
                                         unsigned b0, unsigned b1) {
    asm volatile(
        "mma.sync.aligned.m16n8k16.row.col.f32.bf16.bf16.f32 "
        "{%0,%1,%2,%3}, {%4,%5,%6,%7}, {%8,%9}, {%0,%1,%2,%3};\n"
        : "+f"(c[0]), "+f"(c[1]), "+f"(c[2]), "+f"(c[3])
        : "r"(a0), "r"(a1), "r"(a2), "r"(a3), "r"(b0), "r"(b1));
}
__device__ __forceinline__ void ldsm_x4(unsigned& r0, unsigned& r1, unsigned& r2,
                                        unsigned& r3, const __nv_bfloat16* p) {
    unsigned addr = (unsigned)__cvta_generic_to_shared(p);
    asm volatile("ldmatrix.sync.aligned.m8n8.x4.shared.b16 {%0,%1,%2,%3}, [%4];"
                 : "=r"(r0), "=r"(r1), "=r"(r2), "=r"(r3) : "r"(addr));
}

// GEMM mainloop: C[128x64], A = bf16 hi/lo (two K segments), B pre-split bf16 [N][K]
__device__ __forceinline__ void gemm_tile_bf16(
    const __nv_bfloat16* __restrict__ A0h, const __nv_bfloat16* __restrict__ A0l,
    const __nv_bfloat16* __restrict__ A1h, const __nv_bfloat16* __restrict__ A1l,
    int kSplit, int Ktot,
    const __nv_bfloat16* __restrict__ BTh, const __nv_bfloat16* __restrict__ BTl,
    int m0, int n0,
    __nv_bfloat16* sAh, __nv_bfloat16* sAl, __nv_bfloat16* sBh, __nv_bfloat16* sBl,
    float acc[2][4][4])
{
    int tid  = threadIdx.x;
    int lane = tid & 31, warp = tid >> 5;
    int wM = warp >> 1, wN = warp & 1;

    for (int k0 = 0; k0 < Ktot; k0 += BK) {
        const __nv_bfloat16 *Ah, *Al; int acol;
        if (k0 < kSplit) { Ah = A0h; Al = A0l; acol = k0; }
        else             { Ah = A1h; Al = A1l; acol = k0 - kSplit; }
        // A tile: 128 rows x 32 bf16, 8B chunks
        for (int i = tid; i < BM*8; i += 256) {
            int row = i >> 3, c4 = (i & 7) * 4;
            size_t go = (size_t)(m0 + row)*HH + acol + c4;
            int so = row*KPAD + c4;
            *(uint2*)(sAh + so) = *(const uint2*)(Ah + go);
            *(uint2*)(sAl + so) = *(const uint2*)(Al + go);
        }
        // B tile: 64 rows x 32 bf16
        for (int i = tid; i < BN*8; i += 256) {
            int n = i >> 3, c4 = (i & 7) * 4;
            size_t go = (size_t)(n0 + n)*Ktot + k0 + c4;
            int so = n*KPAD + c4;
            *(uint2*)(sBh + so) = *(const uint2*)(BTh + go);
            *(uint2*)(sBl + so) = *(const uint2*)(BTl + go);
        }
        __syncthreads();

        #pragma unroll
        for (int ks = 0; ks < BK; ks += 16) {
            // A fragments via ldmatrix.x4
            unsigned ah[2][4], al[2][4];
            #pragma unroll
            for (int fm = 0; fm < 2; fm++) {
                int arow = wM*32 + fm*16 + (lane & 15);
                int acol2 = ks + (lane >> 4) * 8;
                ldsm_x4(ah[fm][0], ah[fm][1], ah[fm][2], ah[fm][3], sAh + arow*KPAD + acol2);
                ldsm_x4(al[fm][0], al[fm][1], al[fm][2], al[fm][3], sAl + arow*KPAD + acol2);
            }
            // B fragments: x4 covers two fn at once
            unsigned bh[4][2], bl[4][2];
            #pragma unroll
            for (int fnp = 0; fnp < 2; fnp++) {
                int brow = wN*32 + fnp*16 + (lane & 7) + ((lane >> 4) << 3);
                int bcol = ks + ((lane >> 3) & 1) * 8;
                ldsm_x4(bh[fnp*2][0], bh[fnp*2][1], bh[fnp*2+1][0], bh[fnp*2+1][1],
                        sBh + brow*KPAD + bcol);
                ldsm_x4(bl[fnp*2][0], bl[fnp*2][1], bl[fnp*2+1][0], bl[fnp*2+1][1],
                        sBl + brow*KPAD + bcol);
            }
            #pragma unroll
            for (int fn = 0; fn < 4; fn++) {
                #pragma unroll
                for (int fm = 0; fm < 2; fm++) {
                    mma16816(acc[fm][fn], ah[fm][0], ah[fm][1], ah[fm][2], ah[fm][3],
                             bh[fn][0], bh[fn][1]);
                    mma16816(acc[fm][fn], ah[fm][0], ah[fm][1], ah[fm][2], ah[fm][3],
                             bl[fn][0], bl[fn][1]);
                    mma16816(acc[fm][fn], al[fm][0], al[fm][1], al[fm][2], al[fm][3],
                             bh[fn][0], bh[fn][1]);
                }
            }
        }
        __syncthreads();
    }
}

// ---------------- weight prep (split + transpose to [N][K]) -----------------
__global__ void k_prep_pq(const float* __restrict__ Wm1)
{
    int idx = blockIdx.x*256 + threadIdx.x;   // 256*512
    int k = idx >> 9, n = idx & 511;
    float v = (n < 256) ? Wm1[k*HH + n] : Wm1[(256 + k)*HH + (n - 256)];
    __nv_bfloat16 h = __float2bfloat16(v);
    g_Bpq_hi[n*256 + k] = h;
    g_Bpq_lo[n*256 + k] = __float2bfloat16(v - __bfloat162float(h));
}
__global__ void k_prep_u1(const float* __restrict__ Wu1)
{
    int idx = blockIdx.x*256 + threadIdx.x;   // 512*256
    int k = idx >> 8, n = idx & 255;
    float v = Wu1[k*HH + n];
    __nv_bfloat16 h = __float2bfloat16(v);
    g_Bu1_hi[n*512 + k] = h;
    g_Bu1_lo[n*512 + k] = __float2bfloat16(v - __bfloat162float(h));
}
__global__ void k_prep_u0(const float* __restrict__ Wu0)
{
    int idx = blockIdx.x*256 + threadIdx.x;   // 256*256
    int k = idx >> 8, n = idx & 255;
    float v = Wu0[(256 + k)*HH + n];
    __nv_bfloat16 h = __float2bfloat16(v);
    g_Bu0_hi[n*256 + k] = h;
    g_Bu0_lo[n*256 + k] = __float2bfloat16(v - __bfloat162float(h));
}

// ---------------- split agg fp32 -> bf16 hi/lo -------------------------------
__global__ void k_split_agg()
{
    int i = blockIdx.x * blockDim.x + threadIdx.x;
    int stride = gridDim.x * blockDim.x;
    for (int k = i; k < NN*HH; k += stride) {
        float v = g_agg[k];
        __nv_bfloat16 h = __float2bfloat16(v);
        g_agg_hi[k] = h;
        g_agg_lo[k] = __float2bfloat16(v - __bfloat162float(h));
    }
}

// ---------------- zero agg + dpos -------------------------------------------
__global__ void k_zero()
{
    int i = blockIdx.x * blockDim.x + threadIdx.x;
    int stride = gridDim.x * blockDim.x;
    for (int k = i; k < NN*HH; k += stride) g_agg[k] = 0.f;
    for (int k = i; k < NN*SD; k += stride) g_dpos[k] = 0.f;
}

// ---------------- front-end --------------------------------------------------
__global__ void k_h0(const float* __restrict__ x, const float* __restrict__ W,
                     const float* __restrict__ b)
{
    int bi = blockIdx.x, j = threadIdx.x;
    __shared__ float xr[FF];
    if (j < FF) xr[j] = x[bi*FF + j];
    __syncthreads();
    float acc = b[j];
    #pragma unroll 4
    for (int k = 0; k < FF; k++) acc = fmaf(xr[k], W[k*HH + j], acc);
    g_h0[bi*HH + j] = acc;
}

__global__ void k_meand(const float* __restrict__ P)
{
    int i = blockIdx.x;
    float px = P[i*3+0], py = P[i*3+1], pz = P[i*3+2];
    float s = 0.f;
    for (int j = threadIdx.x; j < NPTS; j += 256) {
        if (j == i) continue;
        float dx = px - P[j*3+0], dy = py - P[j*3+1], dz = pz - P[j*3+2];
        s += sqrtf(dx*dx + dy*dy + dz*dz);
    }
    __shared__ float red[256];
    red[threadIdx.x] = s;
    __syncthreads();
    for (int st = 128; st > 0; st >>= 1) {
        if (threadIdx.x < st) red[threadIdx.x] += red[threadIdx.x + st];
        __syncthreads();
    }
    if (threadIdx.x == 0) g_meand[i] = red[0] / (float)(NPTS - 1);
}

__global__ void k_geo(const float* __restrict__ Wg1, const float* __restrict__ bg1,
                      const float* __restrict__ Wg2, const float* __restrict__ bg2)
{
    int i = blockIdx.x, j = threadIdx.x;
    __shared__ float t[FF];
    float m = g_meand[i];
    if (j < FF) {
        float ws = Wg1[j] + Wg1[FF + j] + Wg1[2*FF + j];
        t[j] = fmaxf(fmaf(m, ws, bg1[j]), 0.f);
    }
    __syncthreads();
    float acc = bg2[j];
    #pragma unroll 4
    for (int k = 0; k < FF; k++) acc = fmaf(t[k], Wg2[k*HH + j], acc);
    g_g[i*HH + j] = acc;
}

__global__ void k_posinit(const float* __restrict__ P)
{
    int i = blockIdx.x * blockDim.x + threadIdx.x;
    if (i < NN*SD) {
        int bn = i / 3, c = i - bn*3;
        int n = bn & (NPTS - 1);
        g_pos[i] = P[n*3 + c];
    }
}

__global__ void k_posupd()
{
    int i = blockIdx.x * blockDim.x + threadIdx.x;
    if (i < NN*SD) g_pos[i] += g_dpos[i] * 0.25f;
}

__global__ void k_oinit(const float* __restrict__ bo, float* __restrict__ out)
{
    int i = blockIdx.x * blockDim.x + threadIdx.x;
    if (i < NN) out[i] = bo[0];
}

// ------- layer-0 low-rank tables ---------------------------------------------
__global__ void __launch_bounds__(256) pq0_kernel(
    const float* __restrict__ Wm, const float* __restrict__ Wu)
{
    __shared__ __align__(16) float sm[TE * HH];
    int tid = threadIdx.x;
    int r0 = blockIdx.x * TE;

    #pragma unroll 4
    for (int e = 0; e < TE; e++) {
        int r = r0 + e;
        const float* row = (r < BB) ? (g_h0 + r*HH) : (g_g + (r - BB)*HH);
        sm[e*HH + tid] = row[tid];
    }
    __syncthreads();

    float accP[TE], accQ[TE], accU[TE];
    #pragma unroll
    for (int e = 0; e < TE; e++) { accP[e] = 0.f; accQ[e] = 0.f; accU[e] = 0.f; }

    const float* wt = Wm + tid;
    const float* wq = Wm + (size_t)HH*HH + tid;
    const float* wu = Wu + tid;
    for (int k4 = 0; k4 < HH/4; k4++) {
        float t0 = wt[(4*k4+0)*HH], t1 = wt[(4*k4+1)*HH];
        float t2 = wt[(4*k4+2)*HH], t3 = wt[(4*k4+3)*HH];
        float q0 = wq[(4*k4+0)*HH], q1 = wq[(4*k4+1)*HH];
        float q2 = wq[(4*k4+2)*HH], q3 = wq[(4*k4+3)*HH];
        float u0 = wu[(4*k4+0)*HH], u1 = wu[(4*k4+1)*HH];
        float u2 = wu[(4*k4+2)*HH], u3 = wu[(4*k4+3)*HH];
        #pragma unroll
        for (int e = 0; e < TE; e++) {
            float4 f = *(const float4*)(sm + e*HH + 4*k4);
            accP[e] = fmaf(f.w, t3, fmaf(f.z, t2, fmaf(f.y, t1, fmaf(f.x, t0, accP[e]))));
            accQ[e] = fmaf(f.w, q3, fmaf(f.z, q2, fmaf(f.y, q1, fmaf(f.x, q0, accQ[e]))));
            accU[e] = fmaf(f.w, u3, fmaf(f.z, u2, fmaf(f.y, u1, fmaf(f.x, u0, accU[e]))));
        }
    }
    #pragma unroll
    for (int e = 0; e < TE; e++) {
        g_P0[(r0 + e)*HH + tid] = accP[e];
        g_Q0[(r0 + e)*HH + tid] = accQ[e];
        g_U0[(r0 + e)*HH + tid] = accU[e];
    }
}

// ---------------- layer-0 edgewise -------------------------------------------
__global__ void __launch_bounds__(256) edge0_kernel(
    const int* __restrict__ src, const int* __restrict__ dst,
    const float* __restrict__ Wm, const float* __restrict__ bm,
    const float* __restrict__ Wp)
{
    __shared__ int ssrc[TE], sdst[TE];
    __shared__ float sd[TE];
    __shared__ float spart[8][TE];
    int tid = threadIdx.x;
    int e0 = blockIdx.x * TE;

    if (tid < TE) {
        int s = src[e0 + tid], t = dst[e0 + tid];
        ssrc[tid] = s; sdst[tid] = t;
        float dx = g_pos[s*3+0] - g_pos[t*3+0];
        float dy = g_pos[s*3+1] - g_pos[t*3+1];
        float dz = g_pos[s*3+2] - g_pos[t*3+2];
        sd[tid] = sqrtf(dx*dx + dy*dy + dz*dz + 1e-12f);
    }
    __syncthreads();

    float wd = Wm[(size_t)512*HH + tid];
    float bj = bm[tid];
    float wp = Wp[tid];

    float m_[TE];
    #pragma unroll 4
    for (int e = 0; e < TE; e++) {
        int s = ssrc[e], t = sdst[e];
        int bs = s >> 11, ns = s & (NPTS-1);
        int bt = t >> 11, nt = t & (NPTS-1);
        float v = g_P0[bs*HH + tid] + g_P0[(BB + ns)*HH + tid]
                + g_Q0[bt*HH + tid] + g_Q0[(BB + nt)*HH + tid];
        v = fmaf(sd[e], wd, v) + bj;
        m_[e] = fmaxf(v, 0.f);
    }

    #pragma unroll 4
    for (int e = 0; e < TE; e++) atomicAdd(g_agg + sdst[e]*HH + tid, m_[e]);

    int lane = tid & 31, wrp = tid >> 5;
    #pragma unroll
    for (int e = 0; e < TE; e++) {
        float v = m_[e] * wp;
        v += __shfl_xor_sync(0xffffffffu, v, 16);
        v += __shfl_xor_sync(0xffffffffu, v, 8);
        v += __shfl_xor_sync(0xffffffffu, v, 4);
        v += __shfl_xor_sync(0xffffffffu, v, 2);
        v += __shfl_xor_sync(0xffffffffu, v, 1);
        if (lane == 0) spart[wrp][e] = v;
    }
    __syncthreads();
    if (tid < TE) {
        float c = spart[0][tid] + spart[1][tid] + spart[2][tid] + spart[3][tid]
                + spart[4][tid] + spart[5][tid] + spart[6][tid] + spart[7][tid];
        int s = ssrc[tid], t = sdst[tid];
        atomicAdd(g_dpos + t*3+0, (g_pos[t*3+0] - g_pos[s*3+0]) * c);
        atomicAdd(g_dpos + t*3+1, (g_pos[t*3+1] - g_pos[s*3+1]) * c);
        atomicAdd(g_dpos + t*3+2, (g_pos[t*3+2] - g_pos[s*3+2]) * c);
    }
}

// ---------------- upd0 (MMA): h = h0[b]+g[n] + relu(agg@Wu_bot + U0 + bu) ---
// writes h as bf16 hi/lo
__global__ void __launch_bounds__(256) upd0_mma(const float* __restrict__ bu)
{
    __shared__ __align__(16) __nv_bfloat16 sAh[BM*KPAD], sAl[BM*KPAD];
    __shared__ __align__(16) __nv_bfloat16 sBh[BN*KPAD], sBl[BN*KPAD];
    float acc[2][4][4];
    #pragma unroll
    for (int a = 0; a < 2; a++)
        #pragma unroll
        for (int b = 0; b < 4; b++)
            #pragma unroll
            for (int c = 0; c < 4; c++) acc[a][b][c] = 0.f;

    int m0 = blockIdx.x * BM;
    int n0 = blockIdx.y * BN;
    gemm_tile_bf16(g_agg_hi, g_agg_lo, g_agg_hi, g_agg_lo, HH, HH,
                   g_Bu0_hi, g_Bu0_lo, m0, n0, sAh, sAl, sBh, sBl, acc);

    int lane = threadIdx.x & 31, warp = threadIdx.x >> 5;
    int g = lane >> 2, tg = lane & 3;
    int wM = warp >> 1, wN = warp & 1;
    int b = m0 >> 11;
    #pragma unroll
    for (int fm = 0; fm < 2; fm++) {
        #pragma unroll
        for (int fn = 0; fn < 4; fn++) {
            int c = n0 + wN*32 + fn*8 + tg*2;
            float b0 = bu[c], b1 = bu[c+1];
            #pragma unroll
            for (int rr = 0; rr < 2; rr++) {
                int m = m0 + wM*32 + fm*16 + g + rr*8;
                int n = m & (NPTS-1);
                float base0 = g_h0[b*HH + c]   + g_g[n*HH + c];
                float base1 = g_h0[b*HH + c+1] + g_g[n*HH + c+1];
                float ua0 = acc[fm][fn][rr*2+0] + g_U0[b*HH + c]   + g_U0[(BB+n)*HH + c]   + b0;
                float ua1 = acc[fm][fn][rr*2+1] + g_U0[b*HH + c+1] + g_U0[(BB+n)*HH + c+1] + b1;
                float o0 = base0 + fmaxf(ua0, 0.f);
                float o1 = base1 + fmaxf(ua1, 0.f);
                __nv_bfloat16 h0_ = __float2bfloat16(o0);
                __nv_bfloat16 h1_ = __float2bfloat16(o1);
                *(unsigned*)(g_h_hi + (size_t)m*HH + c) = pack_bf2(h0_, h1_);
                *(unsigned*)(g_h_lo + (size_t)m*HH + c) =
                    pack_bf2(__float2bfloat16(o0 - __bfloat162float(h0_)),
                             __float2bfloat16(o1 - __bfloat162float(h1_)));
            }
        }
    }
}

// ---------------- pq1 (MMA): g_PQ = h @ [Wm_top | Wm_mid] -------------------
__global__ void __launch_bounds__(256) pq1_mma()
{
    __shared__ __align__(16) __nv_bfloat16 sAh[BM*KPAD], sAl[BM*KPAD];
    __shared__ __align__(16) __nv_bfloat16 sBh[BN*KPAD], sBl[BN*KPAD];
    float acc[2][4][4];
    #pragma unroll
    for (int a = 0; a < 2; a++)
        #pragma unroll
        for (int b = 0; b < 4; b++)
            #pragma unroll
            for (int c = 0; c < 4; c++) acc[a][b][c] = 0.f;

    int m0 = blockIdx.x * BM;
    int n0 = blockIdx.y * BN;
    gemm_tile_bf16(g_h_hi, g_h_lo, g_h_hi, g_h_lo, HH, HH,
                   g_Bpq_hi, g_Bpq_lo, m0, n0, sAh, sAl, sBh, sBl, acc);

    int lane = threadIdx.x & 31, warp = threadIdx.x >> 5;
    int g = lane >> 2, tg = lane & 3;
    int wM = warp >> 1, wN = warp & 1;
    #pragma unroll
    for (int fm = 0; fm < 2; fm++) {
        #pragma unroll
        for (int fn = 0; fn < 4; fn++) {
            int c = n0 + wN*32 + fn*8 + tg*2;
            #pragma unroll
            for (int rr = 0; rr < 2; rr++) {
                int m = m0 + wM*32 + fm*16 + g + rr*8;
                float2 o; o.x = acc[fm][fn][rr*2+0]; o.y = acc[fm][fn][rr*2+1];
                *(float2*)(g_PQ + (size_t)m*512 + c) = o;
            }
        }
    }
}

// ---------------- layer-1 edgewise (no dpos) --------------------------------
__global__ void __launch_bounds__(256) edge1_kernel(
    const int* __restrict__ src, const int* __restrict__ dst,
    const float* __restrict__ Wm, const float* __restrict__ bm)
{
    __shared__ int ssrc[TE], sdst[TE];
    __shared__ float sd[TE];
    int tid = threadIdx.x;
    int e0 = blockIdx.x * TE;

    if (tid < TE) {
        int s = src[e0 + tid], t = dst[e0 + tid];
        ssrc[tid] = s; sdst[tid] = t;
        float dx = g_pos[s*3+0] - g_pos[t*3+0];
        float dy = g_pos[s*3+1] - g_pos[t*3+1];
        float dz = g_pos[s*3+2] - g_pos[t*3+2];
        sd[tid] = sqrtf(dx*dx + dy*dy + dz*dz + 1e-12f);
    }
    __syncthreads();

    float wd = Wm[(size_t)512*HH + tid];
    float bj = bm[tid];

    #pragma unroll 4
    for (int e = 0; e < TE; e++) {
        float v = g_PQ[(size_t)ssrc[e]*512 + tid] + g_PQ[(size_t)sdst[e]*512 + 256 + tid];
        v = fmaf(sd[e], wd, v) + bj;
        atomicAdd(g_agg + sdst[e]*HH + tid, fmaxf(v, 0.f));
    }
}

// ---------------- upd1 (MMA) + fused output ---------------------------------
// out[m] += sum_c (h[m][c] + relu(([h;agg]@Wu)[m][c] + bu[c])) * Wo[c]
__global__ void __launch_bounds__(256) upd1_mma(
    const float* __restrict__ bu, const float* __restrict__ Wo,
    float* __restrict__ out)
{
    __shared__ __align__(16) __nv_bfloat16 sAh[BM*KPAD], sAl[BM*KPAD];
    __shared__ __align__(16) __nv_bfloat16 sBh[BN*KPAD], sBl[BN*KPAD];
    float acc[2][4][4];
    #pragma unroll
    for (int a = 0; a < 2; a++)
        #pragma unroll
        for (int b = 0; b < 4; b++)
            #pragma unroll
            for (int c = 0; c < 4; c++) acc[a][b][c] = 0.f;

    int m0 = blockIdx.x * BM;
    int n0 = blockIdx.y * BN;
    gemm_tile_bf16(g_h_hi, g_h_lo, g_agg_hi, g_agg_lo, HH, 2*HH,
                   g_Bu1_hi, g_Bu1_lo, m0, n0, sAh, sAl, sBh, sBl, acc);

    int lane = threadIdx.x & 31, warp = threadIdx.x >> 5;
    int g = lane >> 2, tg = lane & 3;
    int wM = warp >> 1, wN = warp & 1;
    #pragma unroll
    for (int fm = 0; fm < 2; fm++) {
        #pragma unroll
        for (int rr = 0; rr < 2; rr++) {
            int m = m0 + wM*32 + fm*16 + g + rr*8;
            float rowsum = 0.f;
            #pragma unroll
            for (int fn = 0; fn < 4; fn++) {
                int c = n0 + wN*32 + fn*8 + tg*2;
                unsigned hh = *(const unsigned*)(g_h_hi + (size_t)m*HH + c);
                unsigned hl = *(const unsigned*)(g_h_lo + (size_t)m*HH + c);
                float hold0 = __bfloat162float(__ushort_as_bfloat16((unsigned short)(hh & 0xffff)))
                            + __bfloat162float(__ushort_as_bfloat16((unsigned short)(hl & 0xffff)));
                float hold1 = __bfloat162float(__ushort_as_bfloat16((unsigned short)(hh >> 16)))
                            + __bfloat162float(__ushort_as_bfloat16((unsigned short)(hl >> 16)));
                float o0 = hold0 + fmaxf(acc[fm][fn][rr*2+0] + bu[c], 0.f);
                float o1 = hold1 + fmaxf(acc[fm][fn][rr*2+1] + bu[c+1], 0.f);
                rowsum = fmaf(o0, Wo[c], rowsum);
                rowsum = fmaf(o1, Wo[c+1], rowsum);
            }
            rowsum += __shfl_xor_sync(0xffffffffu, rowsum, 1);
            rowsum += __shfl_xor_sync(0xffffffffu, rowsum, 2);
            if (tg == 0) atomicAdd(out + m, rowsum);
        }
    }
}

// ---------------------------------------------------------------------------
extern "C" void kernel_launch(void* const* d_in, const int* in_sizes, int n_in,
                              void* d_out, int out_size)
{
    const float* x         = (const float*)d_in[0];
    const float* positions = (const float*)d_in[1];
    const float* W_in      = (const float*)d_in[2];
    const float* b_in      = (const float*)d_in[3];
    const float* Wg1       = (const float*)d_in[4];
    const float* bg1       = (const float*)d_in[5];
    const float* Wg2       = (const float*)d_in[6];
    const float* bg2       = (const float*)d_in[7];
    const float* Wm        = (const float*)d_in[8];
    const float* bm        = (const float*)d_in[9];
    const float* Wu        = (const float*)d_in[10];
    const float* bu        = (const float*)d_in[11];
    const float* Wp        = (const float*)d_in[12];
    const float* W_out     = (const float*)d_in[13];
    const float* b_out     = (const float*)d_in[14];
    const int*   edge      = (const int*)d_in[15];
    float* out = (float*)d_out;

    const int* srcp = edge;
    const int* dstp = edge + NE;
    const float* Wm1 = Wm + (size_t)513*HH;
    const float* Wu1 = Wu + (size_t)512*HH;

    k_h0<<<BB, 256>>>(x, W_in, b_in);
    k_meand<<<NPTS, 256>>>(positions);
    k_geo<<<NPTS, 256>>>(Wg1, bg1, Wg2, bg2);
    k_posinit<<<(NN*SD + 255)/256, 256>>>(positions);
    k_prep_pq<<<512, 256>>>(Wm1);
    k_prep_u1<<<512, 256>>>(Wu1);
    k_prep_u0<<<256, 256>>>(Wu);

    // ---- layer 0 ----
    k_zero<<<592, 256>>>();
    pq0_kernel<<<R0/TE, 256>>>(Wm, Wu);
    edge0_kernel<<<NE/TE, 256>>>(srcp, dstp, Wm, bm, Wp);
    k_split_agg<<<592, 256>>>();
    upd0_mma<<<dim3(NN/BM, HH/BN), 256>>>(bu);
    k_posupd<<<(NN*SD + 255)/256, 256>>>();

    // ---- layer 1 ----
    k_zero<<<592, 256>>>();
    pq1_mma<<<dim3(NN/BM, 512/BN), 256>>>();
    edge1_kernel<<<NE/TE, 256>>>(srcp, dstp, Wm1, bm + HH);
    k_split_agg<<<592, 256>>>();
    k_oinit<<<NN/256, 256>>>(b_out, out);
    upd1_mma<<<dim3(NN/BM, HH/BN), 256>>>(bu + HH, W_out, out);
}